// round 2
// baseline (speedup 1.0000x reference)
#include <cuda_runtime.h>

#define B_ 8
#define T_ 2048
#define C_ 768
#define H_ 64
#define BT_ (B_*T_)

// Scratch for projected Q, K, V: [B*T, H] each (device globals — no allocation).
__device__ float g_Q[BT_*H_];
__device__ float g_K[BT_*H_];
__device__ float g_V[BT_*H_];

// ---------------------------------------------------------------------------
// QKV projection: out[m, h] = sum_c x[m, c] * W[h, c]
// M = 16384, K = 768, N = 64 (one 64-wide N tile = full H).
// Block: 256 threads (16x16), each computes a 4x4 microtile of a 64x64 M-N tile.
// gridDim.y selects which weight (0=K, 1=Q, 2=V).
// ---------------------------------------------------------------------------
__global__ __launch_bounds__(256) void qkv_kernel(
    const float* __restrict__ x, const float* __restrict__ Wk,
    const float* __restrict__ Wq, const float* __restrict__ Wv)
{
    __shared__ float Xs[64][17];   // pad 17 -> conflict-free column reads
    __shared__ float Ws[64][17];

    const float* W;
    float* out;
    if (blockIdx.y == 0)      { W = Wk; out = g_K; }
    else if (blockIdx.y == 1) { W = Wq; out = g_Q; }
    else                      { W = Wv; out = g_V; }

    const int tid = threadIdx.x;
    const int tx  = tid & 15;
    const int ty  = tid >> 4;
    const int m0  = blockIdx.x * 64;
    const int lr  = tid >> 2;          // 0..63 (row loaded by this thread)
    const int lq  = (tid & 3) << 2;    // 0,4,8,12 (quad within 16-wide k chunk)

    float acc[4][4] = {};

    for (int k0 = 0; k0 < C_; k0 += 16) {
        float4 xa = *(const float4*)&x[(size_t)(m0 + lr) * C_ + k0 + lq];
        float4 wa = *(const float4*)&W[(size_t)lr * C_ + k0 + lq];
        __syncthreads();   // previous iteration's readers are done
        Xs[lr][lq+0] = xa.x; Xs[lr][lq+1] = xa.y; Xs[lr][lq+2] = xa.z; Xs[lr][lq+3] = xa.w;
        Ws[lr][lq+0] = wa.x; Ws[lr][lq+1] = wa.y; Ws[lr][lq+2] = wa.z; Ws[lr][lq+3] = wa.w;
        __syncthreads();

        #pragma unroll
        for (int kc = 0; kc < 16; kc++) {
            float a[4], b[4];
            #pragma unroll
            for (int i = 0; i < 4; i++) a[i] = Xs[4*ty + i][kc];
            #pragma unroll
            for (int j = 0; j < 4; j++) b[j] = Ws[4*tx + j][kc];
            #pragma unroll
            for (int i = 0; i < 4; i++)
                #pragma unroll
                for (int j = 0; j < 4; j++)
                    acc[i][j] = fmaf(a[i], b[j], acc[i][j]);
        }
    }

    #pragma unroll
    for (int i = 0; i < 4; i++)
        #pragma unroll
        for (int j = 0; j < 4; j++)
            out[(size_t)(m0 + 4*ty + i) * H_ + 4*tx + j] = acc[i][j];
}

// ---------------------------------------------------------------------------
// Flash attention (fp32, causal, NO 1/sqrt(H) scaling — faithful to reference).
// One CTA handles a 64-query tile of one batch. Loops over key tiles kt<=qtile.
// 256 threads (16x16); each owns a 4x4 microtile of S [64q x 64k] and of
// O [64q x 64h]. Online softmax stats (m, l) per query row live in smem.
// Tile loads: each thread loads 4 float4s (rows tid>>4 + 16r, cols (tid&15)*4)
// -> full 64x64 coverage (4096 floats = 256 threads * 16).
// ---------------------------------------------------------------------------
#define PAD 65

__global__ __launch_bounds__(256, 3) void attn_kernel(float* __restrict__ out)
{
    extern __shared__ float sm[];
    float* Qs   = sm;                 // 64*65
    float* Ks   = Qs + 64*PAD;        // 64*65
    float* Ss   = Ks + 64*PAD;        // 64*65  (S tile, then P tile in-place)
    float* Vs   = Ss + 64*PAD;        // 64*64  (pitch 64 -> aligned float4 rows)
    float* mrow = Vs + 64*64;         // 64
    float* lrow = mrow + 64;          // 64
    float* srow = lrow + 64;          // 64  (per-row rescale factor)

    const int b     = blockIdx.y;
    const int qtile = gridDim.x - 1 - blockIdx.x;   // longest CTAs first
    const int tid   = threadIdx.x;
    const int tx    = tid & 15;
    const int ty    = tid >> 4;
    const int lr4   = tid >> 4;         // 0..15  (row group base)
    const int lc4   = (tid & 15) << 2;  // 0..60 step 4 (col quad)

    // Load Q tile [64 x 64] once — 4 float4s per thread.
    {
        const float* Qg = g_Q + (size_t)(b*T_ + qtile*64) * H_;
        #pragma unroll
        for (int r = 0; r < 4; r++) {
            const int row = lr4 + 16*r;
            float4 qv = *(const float4*)&Qg[row*H_ + lc4];
            Qs[row*PAD + lc4+0] = qv.x; Qs[row*PAD + lc4+1] = qv.y;
            Qs[row*PAD + lc4+2] = qv.z; Qs[row*PAD + lc4+3] = qv.w;
        }
    }
    if (tid < 64) { mrow[tid] = -1e30f; lrow[tid] = 0.0f; }

    float o[4][4] = {};

    for (int kt = 0; kt <= qtile; kt++) {
        const float* Kg = g_K + (size_t)(b*T_ + kt*64) * H_;
        const float* Vg = g_V + (size_t)(b*T_ + kt*64) * H_;
        // Stage gmem loads in registers before the barrier.
        float4 kv[4], vv[4];
        #pragma unroll
        for (int r = 0; r < 4; r++) {
            const int row = lr4 + 16*r;
            kv[r] = *(const float4*)&Kg[row*H_ + lc4];
            vv[r] = *(const float4*)&Vg[row*H_ + lc4];
        }
        __syncthreads();   // prior iteration done reading Ks/Vs/Ss
        #pragma unroll
        for (int r = 0; r < 4; r++) {
            const int row = lr4 + 16*r;
            Ks[row*PAD + lc4+0] = kv[r].x; Ks[row*PAD + lc4+1] = kv[r].y;
            Ks[row*PAD + lc4+2] = kv[r].z; Ks[row*PAD + lc4+3] = kv[r].w;
            Vs[row*64  + lc4+0] = vv[r].x; Vs[row*64  + lc4+1] = vv[r].y;
            Vs[row*64  + lc4+2] = vv[r].z; Vs[row*64  + lc4+3] = vv[r].w;
        }
        __syncthreads();

        // S = Q @ K^T  (4x4 per thread)
        float s[4][4] = {};
        #pragma unroll 8
        for (int h = 0; h < 64; h++) {
            float a[4], bb[4];
            #pragma unroll
            for (int i = 0; i < 4; i++) a[i]  = Qs[(4*ty + i)*PAD + h];
            #pragma unroll
            for (int j = 0; j < 4; j++) bb[j] = Ks[(4*tx + j)*PAD + h];
            #pragma unroll
            for (int i = 0; i < 4; i++)
                #pragma unroll
                for (int j = 0; j < 4; j++)
                    s[i][j] = fmaf(a[i], bb[j], s[i][j]);
        }

        // Causal mask on the diagonal tile: key index > query index -> -1e30
        if (kt == qtile) {
            #pragma unroll
            for (int i = 0; i < 4; i++)
                #pragma unroll
                for (int j = 0; j < 4; j++)
                    if (4*tx + j > 4*ty + i) s[i][j] = -1e30f;
        }

        #pragma unroll
        for (int i = 0; i < 4; i++)
            #pragma unroll
            for (int j = 0; j < 4; j++)
                Ss[(4*ty + i)*PAD + 4*tx + j] = s[i][j];
        __syncthreads();

        // Online softmax row pass: one thread per query row.
        if (tid < 64) {
            float mold = mrow[tid];
            float mx = mold;
            #pragma unroll 8
            for (int c = 0; c < 64; c++) mx = fmaxf(mx, Ss[tid*PAD + c]);
            float sumv = 0.0f;
            #pragma unroll 8
            for (int c = 0; c < 64; c++) {
                float p = expf(Ss[tid*PAD + c] - mx);
                Ss[tid*PAD + c] = p;
                sumv += p;
            }
            float scalef = expf(mold - mx);   // 0 on first tile (mold=-1e30)
            lrow[tid] = lrow[tid]*scalef + sumv;
            mrow[tid] = mx;
            srow[tid] = scalef;
        }
        __syncthreads();

        // Rescale accumulators, then O += P @ V.
        float sc[4];
        #pragma unroll
        for (int i = 0; i < 4; i++) sc[i] = srow[4*ty + i];
        #pragma unroll
        for (int i = 0; i < 4; i++)
            #pragma unroll
            for (int j = 0; j < 4; j++)
                o[i][j] *= sc[i];

        #pragma unroll 8
        for (int kk = 0; kk < 64; kk++) {
            float p[4];
            #pragma unroll
            for (int i = 0; i < 4; i++) p[i] = Ss[(4*ty + i)*PAD + kk];
            float4 vq = *(const float4*)&Vs[kk*64 + 4*tx];
            #pragma unroll
            for (int i = 0; i < 4; i++) {
                o[i][0] = fmaf(p[i], vq.x, o[i][0]);
                o[i][1] = fmaf(p[i], vq.y, o[i][1]);
                o[i][2] = fmaf(p[i], vq.z, o[i][2]);
                o[i][3] = fmaf(p[i], vq.w, o[i][3]);
            }
        }
    }

    // Final normalize + store. lrow was written before the last in-loop sync.
    float inv[4];
    #pragma unroll
    for (int i = 0; i < 4; i++) inv[i] = 1.0f / lrow[4*ty + i];
    #pragma unroll
    for (int i = 0; i < 4; i++) {
        const size_t row = (size_t)(b*T_ + qtile*64 + 4*ty + i) * H_;
        #pragma unroll
        for (int j = 0; j < 4; j++)
            out[row + 4*tx + j] = o[i][j] * inv[i];
    }
}

// ---------------------------------------------------------------------------
extern "C" void kernel_launch(void* const* d_in, const int* in_sizes, int n_in,
                              void* d_out, int out_size)
{
    const float* x  = (const float*)d_in[0];
    const float* Wk = (const float*)d_in[1];
    const float* Wq = (const float*)d_in[2];
    const float* Wv = (const float*)d_in[3];
    float* out = (float*)d_out;

    const int smem_attn = (3*64*PAD + 64*64 + 3*64) * (int)sizeof(float);  // 67072 B
    cudaFuncSetAttribute(attn_kernel, cudaFuncAttributeMaxDynamicSharedMemorySize,
                         smem_attn);

    qkv_kernel<<<dim3(BT_/64, 3), 256>>>(x, Wk, Wq, Wv);
    attn_kernel<<<dim3(T_/64, B_), 256, smem_attn>>>(out);
}

// round 3
// speedup vs baseline: 1.4319x; 1.4319x over previous
#include <cuda_runtime.h>

#define B_ 8
#define T_ 2048
#define C_ 768
#define H_ 64
#define BT_ (B_*T_)
#define NQT 32           // number of 64-query tiles per batch

// Scratch for projected Q, K, V: [B*T, H] each (device globals — no allocation).
__device__ float g_Q[BT_*H_];
__device__ float g_K[BT_*H_];
__device__ float g_V[BT_*H_];

// ---------------------------------------------------------------------------
// QKV projection: out[m, h] = sum_c x[m, c] * W[h, c]
// M = 16384, K = 768, N = 64. 256 threads, 4x4 microtile of a 64x64 tile.
// ---------------------------------------------------------------------------
#define XPAD 20   // multiple of 4 -> aligned float4 row reads
__global__ __launch_bounds__(256) void qkv_kernel(
    const float* __restrict__ x, const float* __restrict__ Wk,
    const float* __restrict__ Wq, const float* __restrict__ Wv)
{
    __shared__ float Xs[64][XPAD];
    __shared__ float Ws[64][17];

    const float* W;
    float* out;
    if (blockIdx.y == 0)      { W = Wk; out = g_K; }
    else if (blockIdx.y == 1) { W = Wq; out = g_Q; }
    else                      { W = Wv; out = g_V; }

    const int tid = threadIdx.x;
    const int tx  = tid & 15;
    const int ty  = tid >> 4;
    const int m0  = blockIdx.x * 64;
    const int lr  = tid >> 2;          // 0..63
    const int lq  = (tid & 3) << 2;    // 0,4,8,12

    float acc[4][4] = {};

    for (int k0 = 0; k0 < C_; k0 += 16) {
        float4 xa = *(const float4*)&x[(size_t)(m0 + lr) * C_ + k0 + lq];
        float4 wa = *(const float4*)&W[(size_t)lr * C_ + k0 + lq];
        __syncthreads();
        Xs[lr][lq+0] = xa.x; Xs[lr][lq+1] = xa.y; Xs[lr][lq+2] = xa.z; Xs[lr][lq+3] = xa.w;
        Ws[lr][lq+0] = wa.x; Ws[lr][lq+1] = wa.y; Ws[lr][lq+2] = wa.z; Ws[lr][lq+3] = wa.w;
        __syncthreads();

        #pragma unroll
        for (int kc = 0; kc < 16; kc += 4) {
            float4 a4[4];
            #pragma unroll
            for (int i = 0; i < 4; i++)
                a4[i] = *(const float4*)&Xs[4*ty + i][kc];
            #pragma unroll
            for (int e = 0; e < 4; e++) {
                float b[4];
                #pragma unroll
                for (int j = 0; j < 4; j++) b[j] = Ws[4*tx + j][kc + e];
                const float* ap = (const float*)a4;
                #pragma unroll
                for (int i = 0; i < 4; i++) {
                    float av = ap[4*i + e];
                    #pragma unroll
                    for (int j = 0; j < 4; j++)
                        acc[i][j] = fmaf(av, b[j], acc[i][j]);
                }
            }
        }
    }

    #pragma unroll
    for (int i = 0; i < 4; i++) {
        float4 r = make_float4(acc[i][0], acc[i][1], acc[i][2], acc[i][3]);
        *(float4*)&out[(size_t)(m0 + 4*ty + i) * H_ + 4*tx] = r;
    }
}

// ---------------------------------------------------------------------------
// Flash attention, fp32, causal, no 1/sqrt(H) scaling.
// Grid (16, 8): CTA (p, b) processes qtiles {p, 31-p} of batch b sequentially
// -> every CTA does exactly (p+1) + (32-p) = 33 kt-iterations (perfect balance).
// 256 threads (16x16); 4x4 microtile. Online-softmax stats (m, l) live in
// registers, replicated across the 16-lane row group; reductions via shfl.
// ---------------------------------------------------------------------------
#define QPAD 68   // Qs/Ss pitch: multiple of 4 (aligned float4 rows)
#define KPAD 65   // Ks pitch: odd -> conflict-limited scalar column reads

__global__ __launch_bounds__(256) void attn_kernel(float* __restrict__ out)
{
    extern __shared__ float sm[];
    float* Qs = sm;                 // 64*68
    float* Ss = Qs + 64*QPAD;       // 64*68
    float* Ks = Ss + 64*QPAD;       // 64*65
    float* Vs = Ks + 64*KPAD;       // 64*64

    const int b   = blockIdx.y;
    const int p   = blockIdx.x;     // 0..15
    const int tid = threadIdx.x;
    const int tx  = tid & 15;
    const int ty  = tid >> 4;
    const int lr4 = tid >> 4;          // 0..15
    const int lc4 = (tid & 15) << 2;   // 0..60 step 4

    #pragma unroll
    for (int pick = 0; pick < 2; pick++) {
        const int qtile = pick ? (NQT - 1 - p) : p;

        __syncthreads();   // prior qtile's readers of Qs are done
        {
            const float* Qg = g_Q + (size_t)(b*T_ + qtile*64) * H_;
            #pragma unroll
            for (int r = 0; r < 4; r++) {
                const int row = lr4 + 16*r;
                float4 qv = *(const float4*)&Qg[row*H_ + lc4];
                Qs[row*QPAD + lc4+0] = qv.x; Qs[row*QPAD + lc4+1] = qv.y;
                Qs[row*QPAD + lc4+2] = qv.z; Qs[row*QPAD + lc4+3] = qv.w;
            }
        }

        float o[4][4] = {};
        float mstat[4], lstat[4];
        #pragma unroll
        for (int i = 0; i < 4; i++) { mstat[i] = -1e30f; lstat[i] = 0.0f; }

        for (int kt = 0; kt <= qtile; kt++) {
            const float* Kg = g_K + (size_t)(b*T_ + kt*64) * H_;
            const float* Vg = g_V + (size_t)(b*T_ + kt*64) * H_;
            float4 kv[4], vv[4];
            #pragma unroll
            for (int r = 0; r < 4; r++) {
                const int row = lr4 + 16*r;
                kv[r] = *(const float4*)&Kg[row*H_ + lc4];
                vv[r] = *(const float4*)&Vg[row*H_ + lc4];
            }
            __syncthreads();   // prev iter done reading Ks/Vs/Ss (and Qs store visible)
            #pragma unroll
            for (int r = 0; r < 4; r++) {
                const int row = lr4 + 16*r;
                Ks[row*KPAD + lc4+0] = kv[r].x; Ks[row*KPAD + lc4+1] = kv[r].y;
                Ks[row*KPAD + lc4+2] = kv[r].z; Ks[row*KPAD + lc4+3] = kv[r].w;
                Vs[row*64   + lc4+0] = vv[r].x; Vs[row*64   + lc4+1] = vv[r].y;
                Vs[row*64   + lc4+2] = vv[r].z; Vs[row*64   + lc4+3] = vv[r].w;
            }
            __syncthreads();

            // S = Q @ K^T (4x4 per thread), h unrolled by 4, Q side via float4.
            float s[4][4] = {};
            #pragma unroll 4
            for (int h = 0; h < 64; h += 4) {
                float4 a4[4];
                #pragma unroll
                for (int i = 0; i < 4; i++)
                    a4[i] = *(const float4*)&Qs[(4*ty + i)*QPAD + h];
                #pragma unroll
                for (int e = 0; e < 4; e++) {
                    float bb[4];
                    #pragma unroll
                    for (int j = 0; j < 4; j++) bb[j] = Ks[(4*tx + j)*KPAD + h + e];
                    const float* ap = (const float*)a4;
                    #pragma unroll
                    for (int i = 0; i < 4; i++) {
                        float av = ap[4*i + e];
                        #pragma unroll
                        for (int j = 0; j < 4; j++)
                            s[i][j] = fmaf(av, bb[j], s[i][j]);
                    }
                }
            }

            if (kt == qtile) {   // causal mask on diagonal tile
                #pragma unroll
                for (int i = 0; i < 4; i++)
                    #pragma unroll
                    for (int j = 0; j < 4; j++)
                        if (4*tx + j > 4*ty + i) s[i][j] = -1e30f;
            }

            // Register online softmax; row group = 16 lanes (xor 1,2,4,8 stays inside).
            #pragma unroll
            for (int i = 0; i < 4; i++) {
                float mx = fmaxf(fmaxf(s[i][0], s[i][1]), fmaxf(s[i][2], s[i][3]));
                mx = fmaxf(mx, __shfl_xor_sync(0xffffffffu, mx, 1));
                mx = fmaxf(mx, __shfl_xor_sync(0xffffffffu, mx, 2));
                mx = fmaxf(mx, __shfl_xor_sync(0xffffffffu, mx, 4));
                mx = fmaxf(mx, __shfl_xor_sync(0xffffffffu, mx, 8));
                float mnew = fmaxf(mstat[i], mx);
                float scalef = __expf(mstat[i] - mnew);
                float p0 = __expf(s[i][0] - mnew);
                float p1 = __expf(s[i][1] - mnew);
                float p2 = __expf(s[i][2] - mnew);
                float p3 = __expf(s[i][3] - mnew);
                float sumv = (p0 + p1) + (p2 + p3);
                sumv += __shfl_xor_sync(0xffffffffu, sumv, 1);
                sumv += __shfl_xor_sync(0xffffffffu, sumv, 2);
                sumv += __shfl_xor_sync(0xffffffffu, sumv, 4);
                sumv += __shfl_xor_sync(0xffffffffu, sumv, 8);
                lstat[i] = lstat[i] * scalef + sumv;
                mstat[i] = mnew;
                #pragma unroll
                for (int j = 0; j < 4; j++) o[i][j] *= scalef;
                float4 pr = make_float4(p0, p1, p2, p3);
                *(float4*)&Ss[(4*ty + i)*QPAD + 4*tx] = pr;
            }
            __syncthreads();   // Ss writers -> Ss readers

            // O += P @ V, kk unrolled by 4; P side via broadcast float4.
            #pragma unroll 4
            for (int kk = 0; kk < 64; kk += 4) {
                float4 p4[4];
                #pragma unroll
                for (int i = 0; i < 4; i++)
                    p4[i] = *(const float4*)&Ss[(4*ty + i)*QPAD + kk];
                float4 v0 = *(const float4*)&Vs[(kk+0)*64 + 4*tx];
                float4 v1 = *(const float4*)&Vs[(kk+1)*64 + 4*tx];
                float4 v2 = *(const float4*)&Vs[(kk+2)*64 + 4*tx];
                float4 v3 = *(const float4*)&Vs[(kk+3)*64 + 4*tx];
                #pragma unroll
                for (int i = 0; i < 4; i++) {
                    o[i][0] = fmaf(p4[i].x, v0.x, o[i][0]);
                    o[i][1] = fmaf(p4[i].x, v0.y, o[i][1]);
                    o[i][2] = fmaf(p4[i].x, v0.z, o[i][2]);
                    o[i][3] = fmaf(p4[i].x, v0.w, o[i][3]);
                    o[i][0] = fmaf(p4[i].y, v1.x, o[i][0]);
                    o[i][1] = fmaf(p4[i].y, v1.y, o[i][1]);
                    o[i][2] = fmaf(p4[i].y, v1.z, o[i][2]);
                    o[i][3] = fmaf(p4[i].y, v1.w, o[i][3]);
                    o[i][0] = fmaf(p4[i].z, v2.x, o[i][0]);
                    o[i][1] = fmaf(p4[i].z, v2.y, o[i][1]);
                    o[i][2] = fmaf(p4[i].z, v2.z, o[i][2]);
                    o[i][3] = fmaf(p4[i].z, v2.w, o[i][3]);
                    o[i][0] = fmaf(p4[i].w, v3.x, o[i][0]);
                    o[i][1] = fmaf(p4[i].w, v3.y, o[i][1]);
                    o[i][2] = fmaf(p4[i].w, v3.z, o[i][2]);
                    o[i][3] = fmaf(p4[i].w, v3.w, o[i][3]);
                }
            }
        }

        // Final normalize + store (all state in registers).
        #pragma unroll
        for (int i = 0; i < 4; i++) {
            float inv = 1.0f / lstat[i];
            const size_t row = (size_t)(b*T_ + qtile*64 + 4*ty + i) * H_;
            float4 r = make_float4(o[i][0]*inv, o[i][1]*inv, o[i][2]*inv, o[i][3]*inv);
            *(float4*)&out[row + 4*tx] = r;
        }
    }
}

// ---------------------------------------------------------------------------
extern "C" void kernel_launch(void* const* d_in, const int* in_sizes, int n_in,
                              void* d_out, int out_size)
{
    const float* x  = (const float*)d_in[0];
    const float* Wk = (const float*)d_in[1];
    const float* Wq = (const float*)d_in[2];
    const float* Wv = (const float*)d_in[3];
    float* out = (float*)d_out;

    const int smem_attn = (2*64*QPAD + 64*KPAD + 64*64) * (int)sizeof(float); // 67456 B
    cudaFuncSetAttribute(attn_kernel, cudaFuncAttributeMaxDynamicSharedMemorySize,
                         smem_attn);

    qkv_kernel<<<dim3(BT_/64, 3), 256>>>(x, Wk, Wq, Wv);
    attn_kernel<<<dim3(NQT/2, B_), 256, smem_attn>>>(out);
}

// round 5
// speedup vs baseline: 1.9008x; 1.3275x over previous
#include <cuda_runtime.h>
#include <cstdint>

#define B_ 8
#define T_ 2048
#define C_ 768
#define H_ 64
#define BT_ (B_*T_)
#define NQT 32           // number of 64-query tiles per batch

// Scratch for projected Q, K, V: [B*T, H] each (device globals — no allocation).
__device__ float g_Q[BT_*H_];
__device__ float g_K[BT_*H_];
__device__ float g_V[BT_*H_];

// ---------------------------------------------------------------------------
// tf32 helpers
// ---------------------------------------------------------------------------
__device__ __forceinline__ uint32_t f2tf32(float a) {
    uint32_t r;
    asm("cvt.rna.tf32.f32 %0, %1;" : "=r"(r) : "f"(a));
    return r;
}

__device__ __forceinline__ void mma_tf32(float* d, const uint32_t* a, const uint32_t* b) {
    asm volatile(
        "mma.sync.aligned.m16n8k8.row.col.f32.tf32.tf32.f32 "
        "{%0,%1,%2,%3}, {%4,%5,%6,%7}, {%8,%9}, {%0,%1,%2,%3};"
        : "+f"(d[0]), "+f"(d[1]), "+f"(d[2]), "+f"(d[3])
        : "r"(a[0]), "r"(a[1]), "r"(a[2]), "r"(a[3]), "r"(b[0]), "r"(b[1]));
}

// ---------------------------------------------------------------------------
// QKV projection on tensor cores: out[m,h] = sum_c x[m,c] * W[h,c]
// M=16384, N=H=64, K=C=768. CTA: 128 threads (4 warps), 128x64 output tile.
// tf32 mma with hi/lo input split (3 MMAs) -> ~fp32 precision.
// K staged in chunks of 32, pre-converted to tf32 hi/lo in smem.
// Smem pitch 36: fragment LDS addresses (4r+c) mod 32 all distinct -> conflict-free.
// gridDim.y selects weight (0=K, 1=Q, 2=V).
// ---------------------------------------------------------------------------
#define KCH 32
#define APITCH 36

__global__ __launch_bounds__(128) void qkv_mma_kernel(
    const float* __restrict__ x, const float* __restrict__ Wk,
    const float* __restrict__ Wq, const float* __restrict__ Wv)
{
    extern __shared__ uint32_t qsm[];
    uint32_t* Ah = qsm;                   // 128*36
    uint32_t* Al = Ah + 128*APITCH;       // 128*36
    uint32_t* Bh = Al + 128*APITCH;       // 64*36
    uint32_t* Bl = Bh + 64*APITCH;        // 64*36

    const float* W;
    float* out;
    if (blockIdx.y == 0)      { W = Wk; out = g_K; }
    else if (blockIdx.y == 1) { W = Wq; out = g_Q; }
    else                      { W = Wv; out = g_V; }

    const int tid  = threadIdx.x;
    const int wid  = tid >> 5;          // 0..3
    const int lane = tid & 31;
    const int gid  = lane >> 2;         // 0..7
    const int tig  = lane & 3;          // 0..3
    const int m0   = blockIdx.x * 128;

    const int lrow = tid >> 3;          // 0..15 (row group for loads)
    const int lcol = (tid & 7) << 2;    // 0,4,...,28 (col quad)

    float d[2][8][4] = {};              // [mtile][ntile][frag]

    for (int kc0 = 0; kc0 < C_; kc0 += KCH) {
        // ---- load gmem -> regs (coalesced: 8 lanes x float4 per row seg) ----
        float4 xa[8], wa[4];
        #pragma unroll
        for (int i = 0; i < 8; i++)
            xa[i] = *(const float4*)&x[(size_t)(m0 + lrow + 16*i) * C_ + kc0 + lcol];
        #pragma unroll
        for (int i = 0; i < 4; i++)
            wa[i] = *(const float4*)&W[(size_t)(lrow + 16*i) * C_ + kc0 + lcol];

        __syncthreads();   // previous chunk's compute done reading smem

        // ---- convert to tf32 hi/lo, store to smem ----
        #pragma unroll
        for (int i = 0; i < 8; i++) {
            const int base = (lrow + 16*i) * APITCH + lcol;
            const float* v = (const float*)&xa[i];
            #pragma unroll
            for (int e = 0; e < 4; e++) {
                uint32_t hi = f2tf32(v[e]);
                Ah[base + e] = hi;
                Al[base + e] = f2tf32(v[e] - __uint_as_float(hi));
            }
        }
        #pragma unroll
        for (int i = 0; i < 4; i++) {
            const int base = (lrow + 16*i) * APITCH + lcol;
            const float* v = (const float*)&wa[i];
            #pragma unroll
            for (int e = 0; e < 4; e++) {
                uint32_t hi = f2tf32(v[e]);
                Bh[base + e] = hi;
                Bl[base + e] = f2tf32(v[e] - __uint_as_float(hi));
            }
        }
        __syncthreads();

        // ---- compute: 4 k-steps of 8 ----
        #pragma unroll
        for (int ks = 0; ks < 4; ks++) {
            const int cb = ks * 8;

            uint32_t ah[2][4], al[2][4];
            #pragma unroll
            for (int mt = 0; mt < 2; mt++) {
                const int rw = wid*32 + mt*16;
                ah[mt][0] = Ah[(rw + gid    )*APITCH + cb + tig    ];
                ah[mt][1] = Ah[(rw + gid + 8)*APITCH + cb + tig    ];
                ah[mt][2] = Ah[(rw + gid    )*APITCH + cb + tig + 4];
                ah[mt][3] = Ah[(rw + gid + 8)*APITCH + cb + tig + 4];
                al[mt][0] = Al[(rw + gid    )*APITCH + cb + tig    ];
                al[mt][1] = Al[(rw + gid + 8)*APITCH + cb + tig    ];
                al[mt][2] = Al[(rw + gid    )*APITCH + cb + tig + 4];
                al[mt][3] = Al[(rw + gid + 8)*APITCH + cb + tig + 4];
            }

            uint32_t bh[8][2], bl[8][2];
            #pragma unroll
            for (int nt = 0; nt < 8; nt++) {
                bh[nt][0] = Bh[(nt*8 + gid)*APITCH + cb + tig    ];
                bh[nt][1] = Bh[(nt*8 + gid)*APITCH + cb + tig + 4];
                bl[nt][0] = Bl[(nt*8 + gid)*APITCH + cb + tig    ];
                bl[nt][1] = Bl[(nt*8 + gid)*APITCH + cb + tig + 4];
            }

            #pragma unroll
            for (int mt = 0; mt < 2; mt++)
                #pragma unroll
                for (int nt = 0; nt < 8; nt++) {
                    mma_tf32(d[mt][nt], ah[mt], bh[nt]);   // hi*hi
                    mma_tf32(d[mt][nt], ah[mt], bl[nt]);   // hi*lo
                    mma_tf32(d[mt][nt], al[mt], bh[nt]);   // lo*hi
                }
        }
    }

    // ---- epilogue: fragment layout c0,c1 = (gid, 2tig..2tig+1), c2,c3 = (+8) ----
    #pragma unroll
    for (int mt = 0; mt < 2; mt++) {
        const int r0 = m0 + wid*32 + mt*16 + gid;
        #pragma unroll
        for (int nt = 0; nt < 8; nt++) {
            const int c0 = nt*8 + 2*tig;
            *(float2*)&out[(size_t)r0      * H_ + c0] = make_float2(d[mt][nt][0], d[mt][nt][1]);
            *(float2*)&out[(size_t)(r0+8) * H_ + c0] = make_float2(d[mt][nt][2], d[mt][nt][3]);
        }
    }
}

// ---------------------------------------------------------------------------
// Flash attention, fp32, causal, no 1/sqrt(H) scaling. (unchanged from R3)
// Grid (16, 8): CTA (p, b) processes qtiles {p, 31-p} -> 33 kt-iterations each.
// ---------------------------------------------------------------------------
#define QPAD 68
#define KPAD 65

__global__ __launch_bounds__(256) void attn_kernel(float* __restrict__ out)
{
    extern __shared__ float sm[];
    float* Qs = sm;                 // 64*68
    float* Ss = Qs + 64*QPAD;       // 64*68
    float* Ks = Ss + 64*QPAD;       // 64*65
    float* Vs = Ks + 64*KPAD;       // 64*64

    const int b   = blockIdx.y;
    const int p   = blockIdx.x;
    const int tid = threadIdx.x;
    const int tx  = tid & 15;
    const int ty  = tid >> 4;
    const int lr4 = tid >> 4;
    const int lc4 = (tid & 15) << 2;

    #pragma unroll
    for (int pick = 0; pick < 2; pick++) {
        const int qtile = pick ? (NQT - 1 - p) : p;

        __syncthreads();
        {
            const float* Qg = g_Q + (size_t)(b*T_ + qtile*64) * H_;
            #pragma unroll
            for (int r = 0; r < 4; r++) {
                const int row = lr4 + 16*r;
                float4 qv = *(const float4*)&Qg[row*H_ + lc4];
                Qs[row*QPAD + lc4+0] = qv.x; Qs[row*QPAD + lc4+1] = qv.y;
                Qs[row*QPAD + lc4+2] = qv.z; Qs[row*QPAD + lc4+3] = qv.w;
            }
        }

        float o[4][4] = {};
        float mstat[4], lstat[4];
        #pragma unroll
        for (int i = 0; i < 4; i++) { mstat[i] = -1e30f; lstat[i] = 0.0f; }

        for (int kt = 0; kt <= qtile; kt++) {
            const float* Kg = g_K + (size_t)(b*T_ + kt*64) * H_;
            const float* Vg = g_V + (size_t)(b*T_ + kt*64) * H_;
            float4 kv[4], vv[4];
            #pragma unroll
            for (int r = 0; r < 4; r++) {
                const int row = lr4 + 16*r;
                kv[r] = *(const float4*)&Kg[row*H_ + lc4];
                vv[r] = *(const float4*)&Vg[row*H_ + lc4];
            }
            __syncthreads();
            #pragma unroll
            for (int r = 0; r < 4; r++) {
                const int row = lr4 + 16*r;
                Ks[row*KPAD + lc4+0] = kv[r].x; Ks[row*KPAD + lc4+1] = kv[r].y;
                Ks[row*KPAD + lc4+2] = kv[r].z; Ks[row*KPAD + lc4+3] = kv[r].w;
                Vs[row*64   + lc4+0] = vv[r].x; Vs[row*64   + lc4+1] = vv[r].y;
                Vs[row*64   + lc4+2] = vv[r].z; Vs[row*64   + lc4+3] = vv[r].w;
            }
            __syncthreads();

            float s[4][4] = {};
            #pragma unroll 4
            for (int h = 0; h < 64; h += 4) {
                float4 a4[4];
                #pragma unroll
                for (int i = 0; i < 4; i++)
                    a4[i] = *(const float4*)&Qs[(4*ty + i)*QPAD + h];
                #pragma unroll
                for (int e = 0; e < 4; e++) {
                    float bb[4];
                    #pragma unroll
                    for (int j = 0; j < 4; j++) bb[j] = Ks[(4*tx + j)*KPAD + h + e];
                    const float* ap = (const float*)a4;
                    #pragma unroll
                    for (int i = 0; i < 4; i++) {
                        float av = ap[4*i + e];
                        #pragma unroll
                        for (int j = 0; j < 4; j++)
                            s[i][j] = fmaf(av, bb[j], s[i][j]);
                    }
                }
            }

            if (kt == qtile) {
                #pragma unroll
                for (int i = 0; i < 4; i++)
                    #pragma unroll
                    for (int j = 0; j < 4; j++)
                        if (4*tx + j > 4*ty + i) s[i][j] = -1e30f;
            }

            #pragma unroll
            for (int i = 0; i < 4; i++) {
                float mx = fmaxf(fmaxf(s[i][0], s[i][1]), fmaxf(s[i][2], s[i][3]));
                mx = fmaxf(mx, __shfl_xor_sync(0xffffffffu, mx, 1));
                mx = fmaxf(mx, __shfl_xor_sync(0xffffffffu, mx, 2));
                mx = fmaxf(mx, __shfl_xor_sync(0xffffffffu, mx, 4));
                mx = fmaxf(mx, __shfl_xor_sync(0xffffffffu, mx, 8));
                float mnew = fmaxf(mstat[i], mx);
                float scalef = __expf(mstat[i] - mnew);
                float p0 = __expf(s[i][0] - mnew);
                float p1 = __expf(s[i][1] - mnew);
                float p2 = __expf(s[i][2] - mnew);
                float p3 = __expf(s[i][3] - mnew);
                float sumv = (p0 + p1) + (p2 + p3);
                sumv += __shfl_xor_sync(0xffffffffu, sumv, 1);
                sumv += __shfl_xor_sync(0xffffffffu, sumv, 2);
                sumv += __shfl_xor_sync(0xffffffffu, sumv, 4);
                sumv += __shfl_xor_sync(0xffffffffu, sumv, 8);
                lstat[i] = lstat[i] * scalef + sumv;
                mstat[i] = mnew;
                #pragma unroll
                for (int j = 0; j < 4; j++) o[i][j] *= scalef;
                float4 pr = make_float4(p0, p1, p2, p3);
                *(float4*)&Ss[(4*ty + i)*QPAD + 4*tx] = pr;
            }
            __syncthreads();

            #pragma unroll 4
            for (int kk = 0; kk < 64; kk += 4) {
                float4 p4[4];
                #pragma unroll
                for (int i = 0; i < 4; i++)
                    p4[i] = *(const float4*)&Ss[(4*ty + i)*QPAD + kk];
                float4 v0 = *(const float4*)&Vs[(kk+0)*64 + 4*tx];
                float4 v1 = *(const float4*)&Vs[(kk+1)*64 + 4*tx];
                float4 v2 = *(const float4*)&Vs[(kk+2)*64 + 4*tx];
                float4 v3 = *(const float4*)&Vs[(kk+3)*64 + 4*tx];
                #pragma unroll
                for (int i = 0; i < 4; i++) {
                    o[i][0] = fmaf(p4[i].x, v0.x, o[i][0]);
                    o[i][1] = fmaf(p4[i].x, v0.y, o[i][1]);
                    o[i][2] = fmaf(p4[i].x, v0.z, o[i][2]);
                    o[i][3] = fmaf(p4[i].x, v0.w, o[i][3]);
                    o[i][0] = fmaf(p4[i].y, v1.x, o[i][0]);
                    o[i][1] = fmaf(p4[i].y, v1.y, o[i][1]);
                    o[i][2] = fmaf(p4[i].y, v1.z, o[i][2]);
                    o[i][3] = fmaf(p4[i].y, v1.w, o[i][3]);
                    o[i][0] = fmaf(p4[i].z, v2.x, o[i][0]);
                    o[i][1] = fmaf(p4[i].z, v2.y, o[i][1]);
                    o[i][2] = fmaf(p4[i].z, v2.z, o[i][2]);
                    o[i][3] = fmaf(p4[i].z, v2.w, o[i][3]);
                    o[i][0] = fmaf(p4[i].w, v3.x, o[i][0]);
                    o[i][1] = fmaf(p4[i].w, v3.y, o[i][1]);
                    o[i][2] = fmaf(p4[i].w, v3.z, o[i][2]);
                    o[i][3] = fmaf(p4[i].w, v3.w, o[i][3]);
                }
            }
        }

        #pragma unroll
        for (int i = 0; i < 4; i++) {
            float inv = 1.0f / lstat[i];
            const size_t row = (size_t)(b*T_ + qtile*64 + 4*ty + i) * H_;
            float4 r = make_float4(o[i][0]*inv, o[i][1]*inv, o[i][2]*inv, o[i][3]*inv);
            *(float4*)&out[row + 4*tx] = r;
        }
    }
}

// ---------------------------------------------------------------------------
extern "C" void kernel_launch(void* const* d_in, const int* in_sizes, int n_in,
                              void* d_out, int out_size)
{
    const float* x  = (const float*)d_in[0];
    const float* Wk = (const float*)d_in[1];
    const float* Wq = (const float*)d_in[2];
    const float* Wv = (const float*)d_in[3];
    float* out = (float*)d_out;

    const int smem_qkv  = (2*128*APITCH + 2*64*APITCH) * (int)sizeof(uint32_t); // 55296 B
    const int smem_attn = (2*64*QPAD + 64*KPAD + 64*64) * (int)sizeof(float);   // 67456 B
    cudaFuncSetAttribute(qkv_mma_kernel, cudaFuncAttributeMaxDynamicSharedMemorySize,
                         smem_qkv);
    cudaFuncSetAttribute(attn_kernel, cudaFuncAttributeMaxDynamicSharedMemorySize,
                         smem_attn);

    qkv_mma_kernel<<<dim3(BT_/128, 3), 128, smem_qkv>>>(x, Wk, Wq, Wv);
    attn_kernel<<<dim3(NQT/2, B_), 256, smem_attn>>>(out);
}

// round 8
// speedup vs baseline: 2.0257x; 1.0657x over previous
#include <cuda_runtime.h>
#include <cstdint>

#define B_ 8
#define T_ 2048
#define C_ 768
#define H_ 64
#define BT_ (B_*T_)
#define NQT 32           // number of 64-query tiles per batch

// Scratch for projected Q, K, V: [B*T, H] each (device globals — no allocation).
__device__ float g_Q[BT_*H_];
__device__ float g_K[BT_*H_];
__device__ float g_V[BT_*H_];

// ---------------------------------------------------------------------------
// tf32 helpers
// ---------------------------------------------------------------------------
__device__ __forceinline__ uint32_t f2tf32(float a) {
    uint32_t r;
    asm("cvt.rna.tf32.f32 %0, %1;" : "=r"(r) : "f"(a));
    return r;
}

__device__ __forceinline__ void mma_tf32(float* d, const uint32_t* a, const uint32_t* b) {
    asm volatile(
        "mma.sync.aligned.m16n8k8.row.col.f32.tf32.tf32.f32 "
        "{%0,%1,%2,%3}, {%4,%5,%6,%7}, {%8,%9}, {%0,%1,%2,%3};"
        : "+f"(d[0]), "+f"(d[1]), "+f"(d[2]), "+f"(d[3])
        : "r"(a[0]), "r"(a[1]), "r"(a[2]), "r"(a[3]), "r"(b[0]), "r"(b[1]));
}

// ---------------------------------------------------------------------------
// QKV projection on tensor cores (unchanged, proven): out[m,h] = x @ W^T
// K staged in 32-col chunks -> pitch 36 is valid here (32 cols + 4 pad).
// ---------------------------------------------------------------------------
#define KCH 32
#define APITCH 36

__global__ __launch_bounds__(128) void qkv_mma_kernel(
    const float* __restrict__ x, const float* __restrict__ Wk,
    const float* __restrict__ Wq, const float* __restrict__ Wv)
{
    extern __shared__ uint32_t qsm[];
    uint32_t* Ah = qsm;                   // 128*36
    uint32_t* Al = Ah + 128*APITCH;       // 128*36
    uint32_t* Bh = Al + 128*APITCH;       // 64*36
    uint32_t* Bl = Bh + 64*APITCH;        // 64*36

    const float* W;
    float* out;
    if (blockIdx.y == 0)      { W = Wk; out = g_K; }
    else if (blockIdx.y == 1) { W = Wq; out = g_Q; }
    else                      { W = Wv; out = g_V; }

    const int tid  = threadIdx.x;
    const int wid  = tid >> 5;
    const int lane = tid & 31;
    const int gid  = lane >> 2;
    const int tig  = lane & 3;
    const int m0   = blockIdx.x * 128;

    const int lrow = tid >> 3;
    const int lcol = (tid & 7) << 2;

    float d[2][8][4] = {};

    for (int kc0 = 0; kc0 < C_; kc0 += KCH) {
        float4 xa[8], wa[4];
        #pragma unroll
        for (int i = 0; i < 8; i++)
            xa[i] = *(const float4*)&x[(size_t)(m0 + lrow + 16*i) * C_ + kc0 + lcol];
        #pragma unroll
        for (int i = 0; i < 4; i++)
            wa[i] = *(const float4*)&W[(size_t)(lrow + 16*i) * C_ + kc0 + lcol];

        __syncthreads();

        #pragma unroll
        for (int i = 0; i < 8; i++) {
            const int base = (lrow + 16*i) * APITCH + lcol;
            const float* v = (const float*)&xa[i];
            #pragma unroll
            for (int e = 0; e < 4; e++) {
                uint32_t hi = f2tf32(v[e]);
                Ah[base + e] = hi;
                Al[base + e] = f2tf32(v[e] - __uint_as_float(hi));
            }
        }
        #pragma unroll
        for (int i = 0; i < 4; i++) {
            const int base = (lrow + 16*i) * APITCH + lcol;
            const float* v = (const float*)&wa[i];
            #pragma unroll
            for (int e = 0; e < 4; e++) {
                uint32_t hi = f2tf32(v[e]);
                Bh[base + e] = hi;
                Bl[base + e] = f2tf32(v[e] - __uint_as_float(hi));
            }
        }
        __syncthreads();

        #pragma unroll
        for (int ks = 0; ks < 4; ks++) {
            const int cb = ks * 8;

            uint32_t ah[2][4], al[2][4];
            #pragma unroll
            for (int mt = 0; mt < 2; mt++) {
                const int rw = wid*32 + mt*16;
                ah[mt][0] = Ah[(rw + gid    )*APITCH + cb + tig    ];
                ah[mt][1] = Ah[(rw + gid + 8)*APITCH + cb + tig    ];
                ah[mt][2] = Ah[(rw + gid    )*APITCH + cb + tig + 4];
                ah[mt][3] = Ah[(rw + gid + 8)*APITCH + cb + tig + 4];
                al[mt][0] = Al[(rw + gid    )*APITCH + cb + tig    ];
                al[mt][1] = Al[(rw + gid + 8)*APITCH + cb + tig    ];
                al[mt][2] = Al[(rw + gid    )*APITCH + cb + tig + 4];
                al[mt][3] = Al[(rw + gid + 8)*APITCH + cb + tig + 4];
            }

            uint32_t bh[8][2], bl[8][2];
            #pragma unroll
            for (int nt = 0; nt < 8; nt++) {
                bh[nt][0] = Bh[(nt*8 + gid)*APITCH + cb + tig    ];
                bh[nt][1] = Bh[(nt*8 + gid)*APITCH + cb + tig + 4];
                bl[nt][0] = Bl[(nt*8 + gid)*APITCH + cb + tig    ];
                bl[nt][1] = Bl[(nt*8 + gid)*APITCH + cb + tig + 4];
            }

            #pragma unroll
            for (int mt = 0; mt < 2; mt++)
                #pragma unroll
                for (int nt = 0; nt < 8; nt++) {
                    mma_tf32(d[mt][nt], ah[mt], bh[nt]);
                    mma_tf32(d[mt][nt], ah[mt], bl[nt]);
                    mma_tf32(d[mt][nt], al[mt], bh[nt]);
                }
        }
    }

    #pragma unroll
    for (int mt = 0; mt < 2; mt++) {
        const int r0 = m0 + wid*32 + mt*16 + gid;
        #pragma unroll
        for (int nt = 0; nt < 8; nt++) {
            const int c0 = nt*8 + 2*tig;
            *(float2*)&out[(size_t)r0      * H_ + c0] = make_float2(d[mt][nt][0], d[mt][nt][1]);
            *(float2*)&out[(size_t)(r0+8) * H_ + c0] = make_float2(d[mt][nt][2], d[mt][nt][3]);
        }
    }
}

// ---------------------------------------------------------------------------
// Flash attention on tensor cores. tf32 hi/lo 3-MMA split (~fp32 precision).
// Grid (16, 8): CTA (p, b) processes qtiles {p, 31-p} -> 33 kt-iters each.
// 128 threads / 4 warps; warp w owns q-rows [w*16, w*16+16).
// Pitches: tiles are 64 cols wide. KP=PP=68 (mod 32 = 4 -> B/A-frag reads hit
// banks 4*gid+tig, all distinct). VP=72 (mod 32 = 8 -> 8*tig+gid, all distinct).
// ---------------------------------------------------------------------------
#define KP 68
#define VP 72
#define PP 68

__global__ __launch_bounds__(128) void attn_mma_kernel(float* __restrict__ out)
{
    extern __shared__ uint32_t shb[];
    uint32_t* Kh = shb;               // 64*68
    uint32_t* Kl = Kh + 64*KP;        // 64*68
    uint32_t* Vh = Kl + 64*KP;        // 64*72
    uint32_t* Vl = Vh + 64*VP;        // 64*72
    uint32_t* Ph = Vl + 64*VP;        // 64*68
    uint32_t* Pl = Ph + 64*PP;        // 64*68

    const int b    = blockIdx.y;
    const int p    = blockIdx.x;
    const int tid  = threadIdx.x;
    const int w    = tid >> 5;
    const int lane = tid & 31;
    const int gid  = lane >> 2;
    const int tig  = lane & 3;
    const int w16  = w * 16;
    const int lr   = tid >> 4;          // 0..7  (staging row group)
    const int lc   = (tid & 15) << 2;   // 0..60 (staging col quad)

    for (int pick = 0; pick < 2; pick++) {
        const int qtile = pick ? (NQT - 1 - p) : p;

        // ---- Q A-fragments for all 8 k-steps, hi/lo, held in registers ----
        const float* Qg = g_Q + (size_t)(b*T_ + qtile*64 + w16) * H_;
        uint32_t qh[8][4], ql[8][4];
        #pragma unroll
        for (int ks = 0; ks < 8; ks++) {
            const int c = ks*8 + tig;
            float q0 = Qg[ gid     *H_ + c    ];
            float q1 = Qg[(gid + 8)*H_ + c    ];
            float q2 = Qg[ gid     *H_ + c + 4];
            float q3 = Qg[(gid + 8)*H_ + c + 4];
            qh[ks][0] = f2tf32(q0); ql[ks][0] = f2tf32(q0 - __uint_as_float(qh[ks][0]));
            qh[ks][1] = f2tf32(q1); ql[ks][1] = f2tf32(q1 - __uint_as_float(qh[ks][1]));
            qh[ks][2] = f2tf32(q2); ql[ks][2] = f2tf32(q2 - __uint_as_float(qh[ks][2]));
            qh[ks][3] = f2tf32(q3); ql[ks][3] = f2tf32(q3 - __uint_as_float(qh[ks][3]));
        }

        float o[8][4] = {};
        float mst[2] = {-1e30f, -1e30f};
        float lst[2] = {0.0f, 0.0f};

        for (int kt = 0; kt <= qtile; kt++) {
            // ---- stage K/V tile: gmem -> regs -> (tf32 hi/lo) smem ----
            const float* Kg = g_K + (size_t)(b*T_ + kt*64) * H_;
            const float* Vg = g_V + (size_t)(b*T_ + kt*64) * H_;
            float4 kv[8], vv[8];
            #pragma unroll
            for (int i = 0; i < 8; i++) {
                kv[i] = *(const float4*)&Kg[(lr + 8*i)*H_ + lc];
                vv[i] = *(const float4*)&Vg[(lr + 8*i)*H_ + lc];
            }
            __syncthreads();   // prev iter readers of Kh/Kl/Vh/Vl done
            #pragma unroll
            for (int i = 0; i < 8; i++) {
                const int row = lr + 8*i;
                const float* kp = (const float*)&kv[i];
                const float* vp = (const float*)&vv[i];
                #pragma unroll
                for (int e = 0; e < 4; e++) {
                    uint32_t hk = f2tf32(kp[e]);
                    Kh[row*KP + lc + e] = hk;
                    Kl[row*KP + lc + e] = f2tf32(kp[e] - __uint_as_float(hk));
                    uint32_t hv = f2tf32(vp[e]);
                    Vh[row*VP + lc + e] = hv;
                    Vl[row*VP + lc + e] = f2tf32(vp[e] - __uint_as_float(hv));
                }
            }
            __syncthreads();

            // ---- S = Q @ K^T : 8 ntiles x 8 ksteps x 3 MMAs ----
            float s[8][4] = {};
            #pragma unroll
            for (int ks = 0; ks < 8; ks++) {
                const int cb = ks*8;
                #pragma unroll
                for (int nt = 0; nt < 8; nt++) {
                    const int kr = (nt*8 + gid)*KP + cb + tig;
                    uint32_t bh[2] = { Kh[kr], Kh[kr + 4] };
                    uint32_t bl[2] = { Kl[kr], Kl[kr + 4] };
                    mma_tf32(s[nt], qh[ks], bh);
                    mma_tf32(s[nt], qh[ks], bl);
                    mma_tf32(s[nt], ql[ks], bh);
                }
            }

            // ---- causal mask (diagonal tile only) ----
            if (kt == qtile) {
                #pragma unroll
                for (int nt = 0; nt < 8; nt++) {
                    const int c0 = nt*8 + 2*tig;
                    if (c0     > w16 + gid    ) s[nt][0] = -1e30f;
                    if (c0 + 1 > w16 + gid    ) s[nt][1] = -1e30f;
                    if (c0     > w16 + gid + 8) s[nt][2] = -1e30f;
                    if (c0 + 1 > w16 + gid + 8) s[nt][3] = -1e30f;
                }
            }

            // ---- warp-local online softmax (rows gid, gid+8; quad reduce) ----
            float mx0 = -1e30f, mx1 = -1e30f;
            #pragma unroll
            for (int nt = 0; nt < 8; nt++) {
                mx0 = fmaxf(mx0, fmaxf(s[nt][0], s[nt][1]));
                mx1 = fmaxf(mx1, fmaxf(s[nt][2], s[nt][3]));
            }
            mx0 = fmaxf(mx0, __shfl_xor_sync(0xffffffffu, mx0, 1));
            mx0 = fmaxf(mx0, __shfl_xor_sync(0xffffffffu, mx0, 2));
            mx1 = fmaxf(mx1, __shfl_xor_sync(0xffffffffu, mx1, 1));
            mx1 = fmaxf(mx1, __shfl_xor_sync(0xffffffffu, mx1, 2));
            const float mn0 = fmaxf(mst[0], mx0);
            const float mn1 = fmaxf(mst[1], mx1);
            const float sc0 = __expf(mst[0] - mn0);
            const float sc1 = __expf(mst[1] - mn1);

            float sum0 = 0.0f, sum1 = 0.0f;
            #pragma unroll
            for (int nt = 0; nt < 8; nt++) {
                float p0 = __expf(s[nt][0] - mn0);
                float p1 = __expf(s[nt][1] - mn0);
                float p2 = __expf(s[nt][2] - mn1);
                float p3 = __expf(s[nt][3] - mn1);
                sum0 += p0 + p1;
                sum1 += p2 + p3;
                uint32_t h0 = f2tf32(p0), h1 = f2tf32(p1);
                uint32_t h2 = f2tf32(p2), h3 = f2tf32(p3);
                uint32_t l0 = f2tf32(p0 - __uint_as_float(h0));
                uint32_t l1 = f2tf32(p1 - __uint_as_float(h1));
                uint32_t l2 = f2tf32(p2 - __uint_as_float(h2));
                uint32_t l3 = f2tf32(p3 - __uint_as_float(h3));
                const int b0 = (w16 + gid    )*PP + nt*8 + 2*tig;
                const int b1 = (w16 + gid + 8)*PP + nt*8 + 2*tig;
                *(uint2*)&Ph[b0] = make_uint2(h0, h1);
                *(uint2*)&Pl[b0] = make_uint2(l0, l1);
                *(uint2*)&Ph[b1] = make_uint2(h2, h3);
                *(uint2*)&Pl[b1] = make_uint2(l2, l3);
            }
            sum0 += __shfl_xor_sync(0xffffffffu, sum0, 1);
            sum0 += __shfl_xor_sync(0xffffffffu, sum0, 2);
            sum1 += __shfl_xor_sync(0xffffffffu, sum1, 1);
            sum1 += __shfl_xor_sync(0xffffffffu, sum1, 2);
            lst[0] = lst[0]*sc0 + sum0;  mst[0] = mn0;
            lst[1] = lst[1]*sc1 + sum1;  mst[1] = mn1;
            #pragma unroll
            for (int nt = 0; nt < 8; nt++) {
                o[nt][0] *= sc0; o[nt][1] *= sc0;
                o[nt][2] *= sc1; o[nt][3] *= sc1;
            }
            __syncwarp();   // P layout is warp-local; warp-level ordering suffices

            // ---- O += P @ V ----
            #pragma unroll
            for (int ks = 0; ks < 8; ks++) {
                const int cb = ks*8;
                const int a0 = (w16 + gid    )*PP + cb + tig;
                const int a1 = (w16 + gid + 8)*PP + cb + tig;
                uint32_t ph[4] = { Ph[a0], Ph[a1], Ph[a0 + 4], Ph[a1 + 4] };
                uint32_t pl[4] = { Pl[a0], Pl[a1], Pl[a0 + 4], Pl[a1 + 4] };
                #pragma unroll
                for (int nt = 0; nt < 8; nt++) {
                    const int v0 = (cb + tig    )*VP + nt*8 + gid;
                    const int v1 = (cb + tig + 4)*VP + nt*8 + gid;
                    uint32_t vh[2] = { Vh[v0], Vh[v1] };
                    uint32_t vl[2] = { Vl[v0], Vl[v1] };
                    mma_tf32(o[nt], ph, vh);
                    mma_tf32(o[nt], ph, vl);
                    mma_tf32(o[nt], pl, vh);
                }
            }
        }

        // ---- epilogue: normalize and store ----
        const float inv0 = 1.0f / lst[0];
        const float inv1 = 1.0f / lst[1];
        const size_t r0 = (size_t)(b*T_ + qtile*64 + w16 + gid);
        #pragma unroll
        for (int nt = 0; nt < 8; nt++) {
            const int c0 = nt*8 + 2*tig;
            *(float2*)&out[ r0      * H_ + c0] = make_float2(o[nt][0]*inv0, o[nt][1]*inv0);
            *(float2*)&out[(r0 + 8) * H_ + c0] = make_float2(o[nt][2]*inv1, o[nt][3]*inv1);
        }
    }
}

// ---------------------------------------------------------------------------
extern "C" void kernel_launch(void* const* d_in, const int* in_sizes, int n_in,
                              void* d_out, int out_size)
{
    const float* x  = (const float*)d_in[0];
    const float* Wk = (const float*)d_in[1];
    const float* Wq = (const float*)d_in[2];
    const float* Wv = (const float*)d_in[3];
    float* out = (float*)d_out;

    const int smem_qkv  = (2*128*APITCH + 2*64*APITCH) * (int)sizeof(uint32_t); // 55296 B
    const int smem_attn = (2*64*KP + 2*64*VP + 2*64*PP) * (int)sizeof(uint32_t); // 106496 B
    cudaFuncSetAttribute(qkv_mma_kernel, cudaFuncAttributeMaxDynamicSharedMemorySize,
                         smem_qkv);
    cudaFuncSetAttribute(attn_mma_kernel, cudaFuncAttributeMaxDynamicSharedMemorySize,
                         smem_attn);

    qkv_mma_kernel<<<dim3(BT_/128, 3), 128, smem_qkv>>>(x, Wk, Wq, Wv);
    attn_mma_kernel<<<dim3(NQT/2, B_), 128, smem_attn>>>(out);
}

// round 9
// speedup vs baseline: 2.2572x; 1.1142x over previous
#include <cuda_runtime.h>
#include <cstdint>

#define B_ 8
#define T_ 2048
#define C_ 768
#define H_ 64
#define BT_ (B_*T_)
#define NQT 32           // number of 64-query tiles per batch

// Scratch for projected Q, K, V: [B*T, H] each (device globals — no allocation).
__device__ float g_Q[BT_*H_];
__device__ float g_K[BT_*H_];
__device__ float g_V[BT_*H_];

// ---------------------------------------------------------------------------
// tf32 helpers
// ---------------------------------------------------------------------------
__device__ __forceinline__ uint32_t f2tf32(float a) {
    uint32_t r;
    asm("cvt.rna.tf32.f32 %0, %1;" : "=r"(r) : "f"(a));
    return r;
}

__device__ __forceinline__ void mma_tf32(float* d, const uint32_t* a, const uint32_t* b) {
    asm volatile(
        "mma.sync.aligned.m16n8k8.row.col.f32.tf32.tf32.f32 "
        "{%0,%1,%2,%3}, {%4,%5,%6,%7}, {%8,%9}, {%0,%1,%2,%3};"
        : "+f"(d[0]), "+f"(d[1]), "+f"(d[2]), "+f"(d[3])
        : "r"(a[0]), "r"(a[1]), "r"(a[2]), "r"(a[3]), "r"(b[0]), "r"(b[1]));
}

// ---------------------------------------------------------------------------
// QKV projection on tensor cores (unchanged, proven): out[m,h] = x @ W^T
// ---------------------------------------------------------------------------
#define KCH 32
#define APITCH 36

__global__ __launch_bounds__(128) void qkv_mma_kernel(
    const float* __restrict__ x, const float* __restrict__ Wk,
    const float* __restrict__ Wq, const float* __restrict__ Wv)
{
    extern __shared__ uint32_t qsm[];
    uint32_t* Ah = qsm;                   // 128*36
    uint32_t* Al = Ah + 128*APITCH;       // 128*36
    uint32_t* Bh = Al + 128*APITCH;       // 64*36
    uint32_t* Bl = Bh + 64*APITCH;        // 64*36

    const float* W;
    float* out;
    if (blockIdx.y == 0)      { W = Wk; out = g_K; }
    else if (blockIdx.y == 1) { W = Wq; out = g_Q; }
    else                      { W = Wv; out = g_V; }

    const int tid  = threadIdx.x;
    const int wid  = tid >> 5;
    const int lane = tid & 31;
    const int gid  = lane >> 2;
    const int tig  = lane & 3;
    const int m0   = blockIdx.x * 128;

    const int lrow = tid >> 3;
    const int lcol = (tid & 7) << 2;

    float d[2][8][4] = {};

    for (int kc0 = 0; kc0 < C_; kc0 += KCH) {
        float4 xa[8], wa[4];
        #pragma unroll
        for (int i = 0; i < 8; i++)
            xa[i] = *(const float4*)&x[(size_t)(m0 + lrow + 16*i) * C_ + kc0 + lcol];
        #pragma unroll
        for (int i = 0; i < 4; i++)
            wa[i] = *(const float4*)&W[(size_t)(lrow + 16*i) * C_ + kc0 + lcol];

        __syncthreads();

        #pragma unroll
        for (int i = 0; i < 8; i++) {
            const int base = (lrow + 16*i) * APITCH + lcol;
            const float* v = (const float*)&xa[i];
            #pragma unroll
            for (int e = 0; e < 4; e++) {
                uint32_t hi = f2tf32(v[e]);
                Ah[base + e] = hi;
                Al[base + e] = f2tf32(v[e] - __uint_as_float(hi));
            }
        }
        #pragma unroll
        for (int i = 0; i < 4; i++) {
            const int base = (lrow + 16*i) * APITCH + lcol;
            const float* v = (const float*)&wa[i];
            #pragma unroll
            for (int e = 0; e < 4; e++) {
                uint32_t hi = f2tf32(v[e]);
                Bh[base + e] = hi;
                Bl[base + e] = f2tf32(v[e] - __uint_as_float(hi));
            }
        }
        __syncthreads();

        #pragma unroll
        for (int ks = 0; ks < 4; ks++) {
            const int cb = ks * 8;

            uint32_t ah[2][4], al[2][4];
            #pragma unroll
            for (int mt = 0; mt < 2; mt++) {
                const int rw = wid*32 + mt*16;
                ah[mt][0] = Ah[(rw + gid    )*APITCH + cb + tig    ];
                ah[mt][1] = Ah[(rw + gid + 8)*APITCH + cb + tig    ];
                ah[mt][2] = Ah[(rw + gid    )*APITCH + cb + tig + 4];
                ah[mt][3] = Ah[(rw + gid + 8)*APITCH + cb + tig + 4];
                al[mt][0] = Al[(rw + gid    )*APITCH + cb + tig    ];
                al[mt][1] = Al[(rw + gid + 8)*APITCH + cb + tig    ];
                al[mt][2] = Al[(rw + gid    )*APITCH + cb + tig + 4];
                al[mt][3] = Al[(rw + gid + 8)*APITCH + cb + tig + 4];
            }

            uint32_t bh[8][2], bl[8][2];
            #pragma unroll
            for (int nt = 0; nt < 8; nt++) {
                bh[nt][0] = Bh[(nt*8 + gid)*APITCH + cb + tig    ];
                bh[nt][1] = Bh[(nt*8 + gid)*APITCH + cb + tig + 4];
                bl[nt][0] = Bl[(nt*8 + gid)*APITCH + cb + tig    ];
                bl[nt][1] = Bl[(nt*8 + gid)*APITCH + cb + tig + 4];
            }

            #pragma unroll
            for (int mt = 0; mt < 2; mt++)
                #pragma unroll
                for (int nt = 0; nt < 8; nt++) {
                    mma_tf32(d[mt][nt], ah[mt], bh[nt]);
                    mma_tf32(d[mt][nt], ah[mt], bl[nt]);
                    mma_tf32(d[mt][nt], al[mt], bh[nt]);
                }
        }
    }

    #pragma unroll
    for (int mt = 0; mt < 2; mt++) {
        const int r0 = m0 + wid*32 + mt*16 + gid;
        #pragma unroll
        for (int nt = 0; nt < 8; nt++) {
            const int c0 = nt*8 + 2*tig;
            *(float2*)&out[(size_t)r0      * H_ + c0] = make_float2(d[mt][nt][0], d[mt][nt][1]);
            *(float2*)&out[(size_t)(r0+8) * H_ + c0] = make_float2(d[mt][nt][2], d[mt][nt][3]);
        }
    }
}

// ---------------------------------------------------------------------------
// Flash attention on tensor cores, split-kt across two warp groups.
// Grid (16, 8): CTA (p, b) processes qtiles {p, 31-p} sequentially.
// 256 threads / 8 warps: group g = warps [4g, 4g+4) handles kt ≡ g (mod 2)
// with its own K/V/P smem set and named barrier (g+1). After the kt loop,
// group 1 exports (m, l, O) via smem; group 0 merges states and writes output.
// Pitches: KP=PP=68 (mod 32 = 4), VP=72 (mod 32 = 8) -> conflict-free frags.
// ---------------------------------------------------------------------------
#define KP 68
#define VP 72
#define PP 68
#define GWORDS (2*64*KP + 2*64*VP + 2*64*PP)   // 26624 words per group

#define BAR_SYNC(id) asm volatile("bar.sync %0, %1;" :: "r"(id), "r"(128) : "memory")

__global__ __launch_bounds__(256) void attn_mma_kernel(float* __restrict__ out)
{
    extern __shared__ uint32_t shb[];

    const int b    = blockIdx.y;
    const int p    = blockIdx.x;
    const int tid  = threadIdx.x;
    const int w    = tid >> 5;
    const int g    = w >> 2;            // warp group 0/1
    const int wg   = w & 3;             // warp within group
    const int lane = tid & 31;
    const int gid  = lane >> 2;
    const int tig  = lane & 3;
    const int w16  = wg * 16;
    const int ltid = tid & 127;         // thread id within group
    const int lr   = ltid >> 4;         // 0..7  (staging row group)
    const int lc   = (ltid & 15) << 2;  // 0..60 (staging col quad)

    uint32_t* Kh = shb + g*GWORDS;      // 64*68
    uint32_t* Kl = Kh + 64*KP;          // 64*68
    uint32_t* Vh = Kl + 64*KP;          // 64*72
    uint32_t* Vl = Vh + 64*VP;          // 64*72
    uint32_t* Ph = Vl + 64*VP;          // 64*68
    uint32_t* Pl = Ph + 64*PP;          // 64*68

    // Merge region: reuse group 1's (dead-after-loop) K buffers.
    float* Osm = (float*)(shb + GWORDS);            // 64 x KP floats
    float* Mm  = (float*)(shb + GWORDS + 64*KP);    // 64
    float* Lm  = Mm + 64;                           // 64

    for (int pick = 0; pick < 2; pick++) {
        const int qtile = pick ? (NQT - 1 - p) : p;

        // ---- Q A-fragments for all 8 k-steps, hi/lo, in registers ----
        const float* Qg = g_Q + (size_t)(b*T_ + qtile*64 + w16) * H_;
        uint32_t qh[8][4], ql[8][4];
        #pragma unroll
        for (int ks = 0; ks < 8; ks++) {
            const int c = ks*8 + tig;
            float q0 = Qg[ gid     *H_ + c    ];
            float q1 = Qg[(gid + 8)*H_ + c    ];
            float q2 = Qg[ gid     *H_ + c + 4];
            float q3 = Qg[(gid + 8)*H_ + c + 4];
            qh[ks][0] = f2tf32(q0); ql[ks][0] = f2tf32(q0 - __uint_as_float(qh[ks][0]));
            qh[ks][1] = f2tf32(q1); ql[ks][1] = f2tf32(q1 - __uint_as_float(qh[ks][1]));
            qh[ks][2] = f2tf32(q2); ql[ks][2] = f2tf32(q2 - __uint_as_float(qh[ks][2]));
            qh[ks][3] = f2tf32(q3); ql[ks][3] = f2tf32(q3 - __uint_as_float(qh[ks][3]));
        }

        float o[8][4] = {};
        float mst[2] = {-1e30f, -1e30f};
        float lst[2] = {0.0f, 0.0f};

        for (int kt = g; kt <= qtile; kt += 2) {
            // ---- stage K/V tile: gmem -> regs -> (tf32 hi/lo) smem ----
            const float* Kg = g_K + (size_t)(b*T_ + kt*64) * H_;
            const float* Vg = g_V + (size_t)(b*T_ + kt*64) * H_;
            float4 kv[8], vv[8];
            #pragma unroll
            for (int i = 0; i < 8; i++) {
                kv[i] = *(const float4*)&Kg[(lr + 8*i)*H_ + lc];
                vv[i] = *(const float4*)&Vg[(lr + 8*i)*H_ + lc];
            }
            BAR_SYNC(g+1);   // group's prev-iter readers done
            #pragma unroll
            for (int i = 0; i < 8; i++) {
                const int row = lr + 8*i;
                const float* kp = (const float*)&kv[i];
                const float* vp = (const float*)&vv[i];
                #pragma unroll
                for (int e = 0; e < 4; e++) {
                    uint32_t hk = f2tf32(kp[e]);
                    Kh[row*KP + lc + e] = hk;
                    Kl[row*KP + lc + e] = f2tf32(kp[e] - __uint_as_float(hk));
                    uint32_t hv = f2tf32(vp[e]);
                    Vh[row*VP + lc + e] = hv;
                    Vl[row*VP + lc + e] = f2tf32(vp[e] - __uint_as_float(hv));
                }
            }
            BAR_SYNC(g+1);

            // ---- S = Q @ K^T ----
            float s[8][4] = {};
            #pragma unroll
            for (int ks = 0; ks < 8; ks++) {
                const int cb = ks*8;
                #pragma unroll
                for (int nt = 0; nt < 8; nt++) {
                    const int kr = (nt*8 + gid)*KP + cb + tig;
                    uint32_t bh[2] = { Kh[kr], Kh[kr + 4] };
                    uint32_t bl[2] = { Kl[kr], Kl[kr + 4] };
                    mma_tf32(s[nt], qh[ks], bh);
                    mma_tf32(s[nt], qh[ks], bl);
                    mma_tf32(s[nt], ql[ks], bh);
                }
            }

            // ---- causal mask (diagonal tile only) ----
            if (kt == qtile) {
                #pragma unroll
                for (int nt = 0; nt < 8; nt++) {
                    const int c0 = nt*8 + 2*tig;
                    if (c0     > w16 + gid    ) s[nt][0] = -1e30f;
                    if (c0 + 1 > w16 + gid    ) s[nt][1] = -1e30f;
                    if (c0     > w16 + gid + 8) s[nt][2] = -1e30f;
                    if (c0 + 1 > w16 + gid + 8) s[nt][3] = -1e30f;
                }
            }

            // ---- warp-local online softmax ----
            float mx0 = -1e30f, mx1 = -1e30f;
            #pragma unroll
            for (int nt = 0; nt < 8; nt++) {
                mx0 = fmaxf(mx0, fmaxf(s[nt][0], s[nt][1]));
                mx1 = fmaxf(mx1, fmaxf(s[nt][2], s[nt][3]));
            }
            mx0 = fmaxf(mx0, __shfl_xor_sync(0xffffffffu, mx0, 1));
            mx0 = fmaxf(mx0, __shfl_xor_sync(0xffffffffu, mx0, 2));
            mx1 = fmaxf(mx1, __shfl_xor_sync(0xffffffffu, mx1, 1));
            mx1 = fmaxf(mx1, __shfl_xor_sync(0xffffffffu, mx1, 2));
            const float mn0 = fmaxf(mst[0], mx0);
            const float mn1 = fmaxf(mst[1], mx1);
            const float sc0 = __expf(mst[0] - mn0);
            const float sc1 = __expf(mst[1] - mn1);

            float sum0 = 0.0f, sum1 = 0.0f;
            #pragma unroll
            for (int nt = 0; nt < 8; nt++) {
                float p0 = __expf(s[nt][0] - mn0);
                float p1 = __expf(s[nt][1] - mn0);
                float p2 = __expf(s[nt][2] - mn1);
                float p3 = __expf(s[nt][3] - mn1);
                sum0 += p0 + p1;
                sum1 += p2 + p3;
                uint32_t h0 = f2tf32(p0), h1 = f2tf32(p1);
                uint32_t h2 = f2tf32(p2), h3 = f2tf32(p3);
                uint32_t l0 = f2tf32(p0 - __uint_as_float(h0));
                uint32_t l1 = f2tf32(p1 - __uint_as_float(h1));
                uint32_t l2 = f2tf32(p2 - __uint_as_float(h2));
                uint32_t l3 = f2tf32(p3 - __uint_as_float(h3));
                const int b0 = (w16 + gid    )*PP + nt*8 + 2*tig;
                const int b1 = (w16 + gid + 8)*PP + nt*8 + 2*tig;
                *(uint2*)&Ph[b0] = make_uint2(h0, h1);
                *(uint2*)&Pl[b0] = make_uint2(l0, l1);
                *(uint2*)&Ph[b1] = make_uint2(h2, h3);
                *(uint2*)&Pl[b1] = make_uint2(l2, l3);
            }
            sum0 += __shfl_xor_sync(0xffffffffu, sum0, 1);
            sum0 += __shfl_xor_sync(0xffffffffu, sum0, 2);
            sum1 += __shfl_xor_sync(0xffffffffu, sum1, 1);
            sum1 += __shfl_xor_sync(0xffffffffu, sum1, 2);
            lst[0] = lst[0]*sc0 + sum0;  mst[0] = mn0;
            lst[1] = lst[1]*sc1 + sum1;  mst[1] = mn1;
            #pragma unroll
            for (int nt = 0; nt < 8; nt++) {
                o[nt][0] *= sc0; o[nt][1] *= sc0;
                o[nt][2] *= sc1; o[nt][3] *= sc1;
            }
            __syncwarp();   // P layout is warp-local

            // ---- O += P @ V ----
            #pragma unroll
            for (int ks = 0; ks < 8; ks++) {
                const int cb = ks*8;
                const int a0 = (w16 + gid    )*PP + cb + tig;
                const int a1 = (w16 + gid + 8)*PP + cb + tig;
                uint32_t ph[4] = { Ph[a0], Ph[a1], Ph[a0 + 4], Ph[a1 + 4] };
                uint32_t pl[4] = { Pl[a0], Pl[a1], Pl[a0 + 4], Pl[a1 + 4] };
                #pragma unroll
                for (int nt = 0; nt < 8; nt++) {
                    const int v0 = (cb + tig    )*VP + nt*8 + gid;
                    const int v1 = (cb + tig + 4)*VP + nt*8 + gid;
                    uint32_t vh[2] = { Vh[v0], Vh[v1] };
                    uint32_t vl[2] = { Vl[v0], Vl[v1] };
                    mma_tf32(o[nt], ph, vh);
                    mma_tf32(o[nt], ph, vl);
                    mma_tf32(o[nt], pl, vh);
                }
            }
        }

        // ---- merge the two groups' partial softmax states ----
        if (g == 1) {
            #pragma unroll
            for (int nt = 0; nt < 8; nt++) {
                const int c0 = nt*8 + 2*tig;
                *(float2*)&Osm[(w16 + gid    )*KP + c0] = make_float2(o[nt][0], o[nt][1]);
                *(float2*)&Osm[(w16 + gid + 8)*KP + c0] = make_float2(o[nt][2], o[nt][3]);
            }
            Mm[w16 + gid    ] = mst[0];  Lm[w16 + gid    ] = lst[0];
            Mm[w16 + gid + 8] = mst[1];  Lm[w16 + gid + 8] = lst[1];
        }
        __syncthreads();
        if (g == 0) {
            const float m1a = Mm[w16 + gid    ], l1a = Lm[w16 + gid    ];
            const float m1b = Mm[w16 + gid + 8], l1b = Lm[w16 + gid + 8];
            const float mF0 = fmaxf(mst[0], m1a);
            const float mF1 = fmaxf(mst[1], m1b);
            const float a00 = __expf(mst[0] - mF0), a01 = __expf(m1a - mF0);
            const float a10 = __expf(mst[1] - mF1), a11 = __expf(m1b - mF1);
            const float inv0 = 1.0f / (lst[0]*a00 + l1a*a01);
            const float inv1 = 1.0f / (lst[1]*a10 + l1b*a11);
            const size_t r0 = (size_t)(b*T_ + qtile*64 + w16 + gid);
            #pragma unroll
            for (int nt = 0; nt < 8; nt++) {
                const int c0 = nt*8 + 2*tig;
                float2 u0 = *(const float2*)&Osm[(w16 + gid    )*KP + c0];
                float2 u1 = *(const float2*)&Osm[(w16 + gid + 8)*KP + c0];
                *(float2*)&out[ r0      * H_ + c0] =
                    make_float2((o[nt][0]*a00 + u0.x*a01)*inv0,
                                (o[nt][1]*a00 + u0.y*a01)*inv0);
                *(float2*)&out[(r0 + 8) * H_ + c0] =
                    make_float2((o[nt][2]*a10 + u1.x*a11)*inv1,
                                (o[nt][3]*a10 + u1.y*a11)*inv1);
            }
        }
        __syncthreads();   // merge reads done before next pick reuses buffers
    }
}

// ---------------------------------------------------------------------------
extern "C" void kernel_launch(void* const* d_in, const int* in_sizes, int n_in,
                              void* d_out, int out_size)
{
    const float* x  = (const float*)d_in[0];
    const float* Wk = (const float*)d_in[1];
    const float* Wq = (const float*)d_in[2];
    const float* Wv = (const float*)d_in[3];
    float* out = (float*)d_out;

    const int smem_qkv  = (2*128*APITCH + 2*64*APITCH) * (int)sizeof(uint32_t); // 55296 B
    const int smem_attn = 2 * GWORDS * (int)sizeof(uint32_t);                   // 212992 B
    cudaFuncSetAttribute(qkv_mma_kernel, cudaFuncAttributeMaxDynamicSharedMemorySize,
                         smem_qkv);
    cudaFuncSetAttribute(attn_mma_kernel, cudaFuncAttributeMaxDynamicSharedMemorySize,
                         smem_attn);

    qkv_mma_kernel<<<dim3(BT_/128, 3), 128, smem_qkv>>>(x, Wk, Wq, Wv);
    attn_mma_kernel<<<dim3(NQT/2, B_), 256, smem_attn>>>(out);
}

// round 11
// speedup vs baseline: 2.8269x; 1.2524x over previous
#include <cuda_runtime.h>
#include <cuda_bf16.h>
#include <cstdint>

#define B_ 8
#define T_ 2048
#define C_ 768
#define H_ 64
#define BT_ (B_*T_)
#define NQT 32           // number of 64-query tiles per batch

// Scratch for projected Q, K, V: [B*T, H] each (device globals — no allocation).
__device__ float g_Q[BT_*H_];
__device__ float g_K[BT_*H_];
__device__ float g_V[BT_*H_];

// ---------------------------------------------------------------------------
// helpers
// ---------------------------------------------------------------------------
__device__ __forceinline__ uint32_t f2tf32(float a) {
    uint32_t r;
    asm("cvt.rna.tf32.f32 %0, %1;" : "=r"(r) : "f"(a));
    return r;
}

__device__ __forceinline__ void mma_tf32(float* d, const uint32_t* a, const uint32_t* b) {
    asm volatile(
        "mma.sync.aligned.m16n8k8.row.col.f32.tf32.tf32.f32 "
        "{%0,%1,%2,%3}, {%4,%5,%6,%7}, {%8,%9}, {%0,%1,%2,%3};"
        : "+f"(d[0]), "+f"(d[1]), "+f"(d[2]), "+f"(d[3])
        : "r"(a[0]), "r"(a[1]), "r"(a[2]), "r"(a[3]), "r"(b[0]), "r"(b[1]));
}

__device__ __forceinline__ void mma_bf16(float* d, const uint32_t* a, const uint32_t* b) {
    asm volatile(
        "mma.sync.aligned.m16n8k16.row.col.f32.bf16.bf16.f32 "
        "{%0,%1,%2,%3}, {%4,%5,%6,%7}, {%8,%9}, {%0,%1,%2,%3};"
        : "+f"(d[0]), "+f"(d[1]), "+f"(d[2]), "+f"(d[3])
        : "r"(a[0]), "r"(a[1]), "r"(a[2]), "r"(a[3]), "r"(b[0]), "r"(b[1]));
}

// pack (a,b) into bf16x2 (a in low half); residues packed into lo.
__device__ __forceinline__ uint32_t pack_hilo(float a, float b, uint32_t& lo) {
    __nv_bfloat162 h = __floats2bfloat162_rn(a, b);
    float ha = __bfloat162float(h.x), hb = __bfloat162float(h.y);
    __nv_bfloat162 l = __floats2bfloat162_rn(a - ha, b - hb);
    lo = *reinterpret_cast<uint32_t*>(&l);
    return *reinterpret_cast<uint32_t*>(&h);
}

// ---------------------------------------------------------------------------
// QKV projection on tensor cores (unchanged, proven): out[m,h] = x @ W^T
// ---------------------------------------------------------------------------
#define KCH 32
#define APITCH 36

__global__ __launch_bounds__(128) void qkv_mma_kernel(
    const float* __restrict__ x, const float* __restrict__ Wk,
    const float* __restrict__ Wq, const float* __restrict__ Wv)
{
    extern __shared__ uint32_t qsm[];
    uint32_t* Ah = qsm;                   // 128*36
    uint32_t* Al = Ah + 128*APITCH;       // 128*36
    uint32_t* Bh = Al + 128*APITCH;       // 64*36
    uint32_t* Bl = Bh + 64*APITCH;        // 64*36

    const float* W;
    float* out;
    if (blockIdx.y == 0)      { W = Wk; out = g_K; }
    else if (blockIdx.y == 1) { W = Wq; out = g_Q; }
    else                      { W = Wv; out = g_V; }

    const int tid  = threadIdx.x;
    const int wid  = tid >> 5;
    const int lane = tid & 31;
    const int gid  = lane >> 2;
    const int tig  = lane & 3;
    const int m0   = blockIdx.x * 128;

    const int lrow = tid >> 3;
    const int lcol = (tid & 7) << 2;

    float d[2][8][4] = {};

    for (int kc0 = 0; kc0 < C_; kc0 += KCH) {
        float4 xa[8], wa[4];
        #pragma unroll
        for (int i = 0; i < 8; i++)
            xa[i] = *(const float4*)&x[(size_t)(m0 + lrow + 16*i) * C_ + kc0 + lcol];
        #pragma unroll
        for (int i = 0; i < 4; i++)
            wa[i] = *(const float4*)&W[(size_t)(lrow + 16*i) * C_ + kc0 + lcol];

        __syncthreads();

        #pragma unroll
        for (int i = 0; i < 8; i++) {
            const int base = (lrow + 16*i) * APITCH + lcol;
            const float* v = (const float*)&xa[i];
            #pragma unroll
            for (int e = 0; e < 4; e++) {
                uint32_t hi = f2tf32(v[e]);
                Ah[base + e] = hi;
                Al[base + e] = f2tf32(v[e] - __uint_as_float(hi));
            }
        }
        #pragma unroll
        for (int i = 0; i < 4; i++) {
            const int base = (lrow + 16*i) * APITCH + lcol;
            const float* v = (const float*)&wa[i];
            #pragma unroll
            for (int e = 0; e < 4; e++) {
                uint32_t hi = f2tf32(v[e]);
                Bh[base + e] = hi;
                Bl[base + e] = f2tf32(v[e] - __uint_as_float(hi));
            }
        }
        __syncthreads();

        #pragma unroll
        for (int ks = 0; ks < 4; ks++) {
            const int cb = ks * 8;

            uint32_t ah[2][4], al[2][4];
            #pragma unroll
            for (int mt = 0; mt < 2; mt++) {
                const int rw = wid*32 + mt*16;
                ah[mt][0] = Ah[(rw + gid    )*APITCH + cb + tig    ];
                ah[mt][1] = Ah[(rw + gid + 8)*APITCH + cb + tig    ];
                ah[mt][2] = Ah[(rw + gid    )*APITCH + cb + tig + 4];
                ah[mt][3] = Ah[(rw + gid + 8)*APITCH + cb + tig + 4];
                al[mt][0] = Al[(rw + gid    )*APITCH + cb + tig    ];
                al[mt][1] = Al[(rw + gid + 8)*APITCH + cb + tig    ];
                al[mt][2] = Al[(rw + gid    )*APITCH + cb + tig + 4];
                al[mt][3] = Al[(rw + gid + 8)*APITCH + cb + tig + 4];
            }

            uint32_t bh[8][2], bl[8][2];
            #pragma unroll
            for (int nt = 0; nt < 8; nt++) {
                bh[nt][0] = Bh[(nt*8 + gid)*APITCH + cb + tig    ];
                bh[nt][1] = Bh[(nt*8 + gid)*APITCH + cb + tig + 4];
                bl[nt][0] = Bl[(nt*8 + gid)*APITCH + cb + tig    ];
                bl[nt][1] = Bl[(nt*8 + gid)*APITCH + cb + tig + 4];
            }

            #pragma unroll
            for (int mt = 0; mt < 2; mt++)
                #pragma unroll
                for (int nt = 0; nt < 8; nt++) {
                    mma_tf32(d[mt][nt], ah[mt], bh[nt]);
                    mma_tf32(d[mt][nt], ah[mt], bl[nt]);
                    mma_tf32(d[mt][nt], al[mt], bh[nt]);
                }
        }
    }

    #pragma unroll
    for (int mt = 0; mt < 2; mt++) {
        const int r0 = m0 + wid*32 + mt*16 + gid;
        #pragma unroll
        for (int nt = 0; nt < 8; nt++) {
            const int c0 = nt*8 + 2*tig;
            *(float2*)&out[(size_t)r0      * H_ + c0] = make_float2(d[mt][nt][0], d[mt][nt][1]);
            *(float2*)&out[(size_t)(r0+8) * H_ + c0] = make_float2(d[mt][nt][2], d[mt][nt][3]);
        }
    }
}

// ---------------------------------------------------------------------------
// Flash attention on tensor cores — bf16 m16n8k16 with hi/lo 3-MMA split.
// Grid (16, 8): CTA (p, b) processes qtiles {p, 31-p} sequentially.
// 256 threads / 8 warps: group g handles kt ≡ g (mod 2), own K/V smem +
// named barrier. P stays in registers: C-frag of S == A-frag of m16n8k16.
// K smem: rows = 64 keys, cols = 32 packed bf16x2 along h. Pitch 36
//   (≡4 mod 32 -> B-frag lanes 4*gid+tig conflict-free).
// V smem: rows = 32 key-PAIRS (packed along keys), cols = 64 h values.
//   Pitch 72 >= 64 cols (≡8 mod 32 -> B-frag lanes 8*tig+gid conflict-free).
// ---------------------------------------------------------------------------
#define KPITCH 36
#define VPITCH 72
#define GWORDS (2*64*KPITCH + 2*32*VPITCH)   // 9216 words per group

#define BAR_SYNC(id) asm volatile("bar.sync %0, %1;" :: "r"(id), "r"(128) : "memory")

__global__ __launch_bounds__(256) void attn_mma_kernel(float* __restrict__ out)
{
    extern __shared__ uint32_t shb[];

    const int b    = blockIdx.y;
    const int p    = blockIdx.x;
    const int tid  = threadIdx.x;
    const int w    = tid >> 5;
    const int g    = w >> 2;            // warp group 0/1
    const int wg   = w & 3;             // warp within group
    const int lane = tid & 31;
    const int gid  = lane >> 2;
    const int tig  = lane & 3;
    const int w16  = wg * 16;
    const int ltid = tid & 127;

    // staging assignments
    const int krow = ltid >> 1;            // 0..63 (K row)
    const int kcb  = (ltid & 1) * 32;      // col block 0/32 (h)
    const int vkp  = ltid >> 2;            // 0..31 (V key-pair row)
    const int vcb  = (ltid & 3) * 16;      // h block 0/16/32/48

    uint32_t* Khi = shb + g*GWORDS;        // 64*36
    uint32_t* Klo = Khi + 64*KPITCH;       // 64*36
    uint32_t* Vhi = Klo + 64*KPITCH;       // 32*72
    uint32_t* Vlo = Vhi + 32*VPITCH;       // 32*72

    // Merge region reuses group 1's K buffers (4608 words, dead after loop).
    float* Osm = (float*)(shb + GWORDS);   // 64 x 66 = 4224
    float* Mm  = Osm + 64*66;              // 64
    float* Lm  = Mm + 64;                  // 64   (total 4352 < 4608)

    for (int pick = 0; pick < 2; pick++) {
        const int qtile = pick ? (NQT - 1 - p) : p;

        // ---- Q A-fragments (bf16 hi/lo packed pairs), in registers ----
        const float* Qg = g_Q + (size_t)(b*T_ + qtile*64 + w16) * H_;
        uint32_t qh[4][4], ql[4][4];
        #pragma unroll
        for (int ks = 0; ks < 4; ks++) {
            float2 f0 = *(const float2*)&Qg[ gid     *H_ + ks*16 + 2*tig    ];
            float2 f1 = *(const float2*)&Qg[(gid + 8)*H_ + ks*16 + 2*tig    ];
            float2 f2 = *(const float2*)&Qg[ gid     *H_ + ks*16 + 2*tig + 8];
            float2 f3 = *(const float2*)&Qg[(gid + 8)*H_ + ks*16 + 2*tig + 8];
            qh[ks][0] = pack_hilo(f0.x, f0.y, ql[ks][0]);
            qh[ks][1] = pack_hilo(f1.x, f1.y, ql[ks][1]);
            qh[ks][2] = pack_hilo(f2.x, f2.y, ql[ks][2]);
            qh[ks][3] = pack_hilo(f3.x, f3.y, ql[ks][3]);
        }

        float o[8][4] = {};
        float mst[2] = {-1e30f, -1e30f};
        float lst[2] = {0.0f, 0.0f};

        for (int kt = g; kt <= qtile; kt += 2) {
            // ---- stage K/V: gmem -> regs -> packed bf16x2 hi/lo smem ----
            const float* Kg = g_K + (size_t)(b*T_ + kt*64) * H_;
            const float* Vg = g_V + (size_t)(b*T_ + kt*64) * H_;
            float4 kf[8];
            #pragma unroll
            for (int i = 0; i < 8; i++)
                kf[i] = *(const float4*)&Kg[krow*H_ + kcb + 4*i];
            float4 va[4], vb[4];
            #pragma unroll
            for (int i = 0; i < 4; i++) {
                va[i] = *(const float4*)&Vg[(2*vkp    )*H_ + vcb + 4*i];
                vb[i] = *(const float4*)&Vg[(2*vkp + 1)*H_ + vcb + 4*i];
            }
            BAR_SYNC(g+1);   // group's prev-iter readers done
            #pragma unroll
            for (int i = 0; i < 8; i++) {
                const int c = (kcb >> 1) + 2*i;    // packed-h index
                uint32_t lo;
                Khi[krow*KPITCH + c    ] = pack_hilo(kf[i].x, kf[i].y, lo);
                Klo[krow*KPITCH + c    ] = lo;
                Khi[krow*KPITCH + c + 1] = pack_hilo(kf[i].z, kf[i].w, lo);
                Klo[krow*KPITCH + c + 1] = lo;
            }
            #pragma unroll
            for (int i = 0; i < 4; i++) {
                const float* pa = (const float*)&va[i];
                const float* pb = (const float*)&vb[i];
                #pragma unroll
                for (int e = 0; e < 4; e++) {
                    uint32_t lo;
                    Vhi[vkp*VPITCH + vcb + 4*i + e] = pack_hilo(pa[e], pb[e], lo);
                    Vlo[vkp*VPITCH + vcb + 4*i + e] = lo;
                }
            }
            BAR_SYNC(g+1);

            // ---- S = Q @ K^T : 4 ksteps x 8 ntiles x 3 MMAs ----
            float s[8][4] = {};
            #pragma unroll
            for (int ks = 0; ks < 4; ks++) {
                #pragma unroll
                for (int nt = 0; nt < 8; nt++) {
                    const int kr = (nt*8 + gid)*KPITCH + ks*8 + tig;
                    uint32_t bh[2] = { Khi[kr], Khi[kr + 4] };
                    uint32_t bl[2] = { Klo[kr], Klo[kr + 4] };
                    mma_bf16(s[nt], qh[ks], bh);
                    mma_bf16(s[nt], qh[ks], bl);
                    mma_bf16(s[nt], ql[ks], bh);
                }
            }

            // ---- causal mask (diagonal tile only) ----
            if (kt == qtile) {
                #pragma unroll
                for (int nt = 0; nt < 8; nt++) {
                    const int c0 = nt*8 + 2*tig;
                    if (c0     > w16 + gid    ) s[nt][0] = -1e30f;
                    if (c0 + 1 > w16 + gid    ) s[nt][1] = -1e30f;
                    if (c0     > w16 + gid + 8) s[nt][2] = -1e30f;
                    if (c0 + 1 > w16 + gid + 8) s[nt][3] = -1e30f;
                }
            }

            // ---- warp-local online softmax; P packed to bf16 A-frags ----
            float mx0 = -1e30f, mx1 = -1e30f;
            #pragma unroll
            for (int nt = 0; nt < 8; nt++) {
                mx0 = fmaxf(mx0, fmaxf(s[nt][0], s[nt][1]));
                mx1 = fmaxf(mx1, fmaxf(s[nt][2], s[nt][3]));
            }
            mx0 = fmaxf(mx0, __shfl_xor_sync(0xffffffffu, mx0, 1));
            mx0 = fmaxf(mx0, __shfl_xor_sync(0xffffffffu, mx0, 2));
            mx1 = fmaxf(mx1, __shfl_xor_sync(0xffffffffu, mx1, 1));
            mx1 = fmaxf(mx1, __shfl_xor_sync(0xffffffffu, mx1, 2));
            const float mn0 = fmaxf(mst[0], mx0);
            const float mn1 = fmaxf(mst[1], mx1);
            const float sc0 = __expf(mst[0] - mn0);
            const float sc1 = __expf(mst[1] - mn1);

            float sum0 = 0.0f, sum1 = 0.0f;
            uint32_t ph[16], plr[16];
            #pragma unroll
            for (int nt = 0; nt < 8; nt++) {
                float p0 = __expf(s[nt][0] - mn0);
                float p1 = __expf(s[nt][1] - mn0);
                float p2 = __expf(s[nt][2] - mn1);
                float p3 = __expf(s[nt][3] - mn1);
                sum0 += p0 + p1;
                sum1 += p2 + p3;
                ph[2*nt    ] = pack_hilo(p0, p1, plr[2*nt    ]);
                ph[2*nt + 1] = pack_hilo(p2, p3, plr[2*nt + 1]);
            }
            sum0 += __shfl_xor_sync(0xffffffffu, sum0, 1);
            sum0 += __shfl_xor_sync(0xffffffffu, sum0, 2);
            sum1 += __shfl_xor_sync(0xffffffffu, sum1, 1);
            sum1 += __shfl_xor_sync(0xffffffffu, sum1, 2);
            lst[0] = lst[0]*sc0 + sum0;  mst[0] = mn0;
            lst[1] = lst[1]*sc1 + sum1;  mst[1] = mn1;
            #pragma unroll
            for (int nt = 0; nt < 8; nt++) {
                o[nt][0] *= sc0; o[nt][1] *= sc0;
                o[nt][2] *= sc1; o[nt][3] *= sc1;
            }

            // ---- O += P @ V (P A-frags straight from registers) ----
            #pragma unroll
            for (int ks = 0; ks < 4; ks++) {
                #pragma unroll
                for (int nt = 0; nt < 8; nt++) {
                    const int v0 = (ks*8 + tig)*VPITCH + nt*8 + gid;
                    const int v1 = v0 + 4*VPITCH;
                    uint32_t vh[2] = { Vhi[v0], Vhi[v1] };
                    uint32_t vl[2] = { Vlo[v0], Vlo[v1] };
                    mma_bf16(o[nt], &ph[4*ks],  vh);
                    mma_bf16(o[nt], &ph[4*ks],  vl);
                    mma_bf16(o[nt], &plr[4*ks], vh);
                }
            }
        }

        // ---- merge the two groups' partial softmax states ----
        if (g == 1) {
            #pragma unroll
            for (int nt = 0; nt < 8; nt++) {
                const int c0 = nt*8 + 2*tig;
                *(float2*)&Osm[(w16 + gid    )*66 + c0] = make_float2(o[nt][0], o[nt][1]);
                *(float2*)&Osm[(w16 + gid + 8)*66 + c0] = make_float2(o[nt][2], o[nt][3]);
            }
            Mm[w16 + gid    ] = mst[0];  Lm[w16 + gid    ] = lst[0];
            Mm[w16 + gid + 8] = mst[1];  Lm[w16 + gid + 8] = lst[1];
        }
        __syncthreads();
        if (g == 0) {
            const float m1a = Mm[w16 + gid    ], l1a = Lm[w16 + gid    ];
            const float m1b = Mm[w16 + gid + 8], l1b = Lm[w16 + gid + 8];
            const float mF0 = fmaxf(mst[0], m1a);
            const float mF1 = fmaxf(mst[1], m1b);
            const float a00 = __expf(mst[0] - mF0), a01 = __expf(m1a - mF0);
            const float a10 = __expf(mst[1] - mF1), a11 = __expf(m1b - mF1);
            const float inv0 = 1.0f / (lst[0]*a00 + l1a*a01);
            const float inv1 = 1.0f / (lst[1]*a10 + l1b*a11);
            const size_t r0 = (size_t)(b*T_ + qtile*64 + w16 + gid);
            #pragma unroll
            for (int nt = 0; nt < 8; nt++) {
                const int c0 = nt*8 + 2*tig;
                float2 u0 = *(const float2*)&Osm[(w16 + gid    )*66 + c0];
                float2 u1 = *(const float2*)&Osm[(w16 + gid + 8)*66 + c0];
                *(float2*)&out[ r0      * H_ + c0] =
                    make_float2((o[nt][0]*a00 + u0.x*a01)*inv0,
                                (o[nt][1]*a00 + u0.y*a01)*inv0);
                *(float2*)&out[(r0 + 8) * H_ + c0] =
                    make_float2((o[nt][2]*a10 + u1.x*a11)*inv1,
                                (o[nt][3]*a10 + u1.y*a11)*inv1);
            }
        }
        __syncthreads();   // merge reads done before next pick reuses buffers
    }
}

// ---------------------------------------------------------------------------
extern "C" void kernel_launch(void* const* d_in, const int* in_sizes, int n_in,
                              void* d_out, int out_size)
{
    const float* x  = (const float*)d_in[0];
    const float* Wk = (const float*)d_in[1];
    const float* Wq = (const float*)d_in[2];
    const float* Wv = (const float*)d_in[3];
    float* out = (float*)d_out;

    const int smem_qkv  = (2*128*APITCH + 2*64*APITCH) * (int)sizeof(uint32_t); // 55296 B
    const int smem_attn = 2 * GWORDS * (int)sizeof(uint32_t);                   // 73728 B
    cudaFuncSetAttribute(qkv_mma_kernel, cudaFuncAttributeMaxDynamicSharedMemorySize,
                         smem_qkv);
    cudaFuncSetAttribute(attn_mma_kernel, cudaFuncAttributeMaxDynamicSharedMemorySize,
                         smem_attn);

    qkv_mma_kernel<<<dim3(BT_/128, 3), 128, smem_qkv>>>(x, Wk, Wq, Wv);
    attn_mma_kernel<<<dim3(NQT/2, B_), 256, smem_attn>>>(out);
}

// round 12
// speedup vs baseline: 3.5417x; 1.2529x over previous
#include <cuda_runtime.h>
#include <cuda_bf16.h>
#include <cstdint>

#define B_ 8
#define T_ 2048
#define C_ 768
#define H_ 64
#define BT_ (B_*T_)
#define NQT 32           // number of 64-query tiles per batch

// Scratch for projected Q, K, V: [B*T, H] each (device globals — no allocation).
__device__ float g_Q[BT_*H_];
__device__ float g_K[BT_*H_];
__device__ float g_V[BT_*H_];

// ---------------------------------------------------------------------------
// helpers
// ---------------------------------------------------------------------------
__device__ __forceinline__ void mma_bf16(float* d, const uint32_t* a, const uint32_t* b) {
    asm volatile(
        "mma.sync.aligned.m16n8k16.row.col.f32.bf16.bf16.f32 "
        "{%0,%1,%2,%3}, {%4,%5,%6,%7}, {%8,%9}, {%0,%1,%2,%3};"
        : "+f"(d[0]), "+f"(d[1]), "+f"(d[2]), "+f"(d[3])
        : "r"(a[0]), "r"(a[1]), "r"(a[2]), "r"(a[3]), "r"(b[0]), "r"(b[1]));
}

// pack (a,b) into bf16x2 (a in low half); residues packed into lo.
__device__ __forceinline__ uint32_t pack_hilo(float a, float b, uint32_t& lo) {
    __nv_bfloat162 h = __floats2bfloat162_rn(a, b);
    float ha = __bfloat162float(h.x), hb = __bfloat162float(h.y);
    __nv_bfloat162 l = __floats2bfloat162_rn(a - ha, b - hb);
    lo = *reinterpret_cast<uint32_t*>(&l);
    return *reinterpret_cast<uint32_t*>(&h);
}

// ---------------------------------------------------------------------------
// QKV projection on tensor cores — bf16 m16n8k16 hi/lo split.
// out[m,h] = sum_c x[m,c] * W[h,c].  M=16384, N=64, K=768.
// CTA: 128 threads / 4 warps, 128x64 output tile; gridDim.y = weight select.
// K staged in chunks of 32 floats = 16 packed bf16x2 cols; 2 k16-steps/chunk.
// Smem pitch 20 (>=16 cols; 20*gid+tig mod 32 hits all banks -> conflict-free).
// ---------------------------------------------------------------------------
#define KCH 32
#define QP 20

__global__ __launch_bounds__(128) void qkv_mma_kernel(
    const float* __restrict__ x, const float* __restrict__ Wk,
    const float* __restrict__ Wq, const float* __restrict__ Wv)
{
    extern __shared__ uint32_t qsm[];
    uint32_t* Ahi = qsm;                  // 128*20
    uint32_t* Alo = Ahi + 128*QP;         // 128*20
    uint32_t* Bhi = Alo + 128*QP;         // 64*20
    uint32_t* Blo = Bhi + 64*QP;          // 64*20

    const float* W;
    float* out;
    if (blockIdx.y == 0)      { W = Wk; out = g_K; }
    else if (blockIdx.y == 1) { W = Wq; out = g_Q; }
    else                      { W = Wv; out = g_V; }

    const int tid  = threadIdx.x;
    const int wid  = tid >> 5;
    const int lane = tid & 31;
    const int gid  = lane >> 2;
    const int tig  = lane & 3;
    const int m0   = blockIdx.x * 128;

    const int lrow = tid >> 3;            // 0..15
    const int lcol = (tid & 7) << 2;      // 0,4,...,28 (float col)
    const int pcol = lcol >> 1;           // packed col base: 0,2,...,14

    float d[2][8][4] = {};

    for (int kc0 = 0; kc0 < C_; kc0 += KCH) {
        float4 xa[8], wa[4];
        #pragma unroll
        for (int i = 0; i < 8; i++)
            xa[i] = *(const float4*)&x[(size_t)(m0 + lrow + 16*i) * C_ + kc0 + lcol];
        #pragma unroll
        for (int i = 0; i < 4; i++)
            wa[i] = *(const float4*)&W[(size_t)(lrow + 16*i) * C_ + kc0 + lcol];

        __syncthreads();   // previous chunk's compute done reading smem

        #pragma unroll
        for (int i = 0; i < 8; i++) {
            const int base = (lrow + 16*i) * QP + pcol;
            uint32_t lo;
            Ahi[base    ] = pack_hilo(xa[i].x, xa[i].y, lo);  Alo[base    ] = lo;
            Ahi[base + 1] = pack_hilo(xa[i].z, xa[i].w, lo);  Alo[base + 1] = lo;
        }
        #pragma unroll
        for (int i = 0; i < 4; i++) {
            const int base = (lrow + 16*i) * QP + pcol;
            uint32_t lo;
            Bhi[base    ] = pack_hilo(wa[i].x, wa[i].y, lo);  Blo[base    ] = lo;
            Bhi[base + 1] = pack_hilo(wa[i].z, wa[i].w, lo);  Blo[base + 1] = lo;
        }
        __syncthreads();

        #pragma unroll
        for (int ks = 0; ks < 2; ks++) {
            const int cb = ks * 8;

            uint32_t ah[2][4], al[2][4];
            #pragma unroll
            for (int mt = 0; mt < 2; mt++) {
                const int rw = wid*32 + mt*16;
                ah[mt][0] = Ahi[(rw + gid    )*QP + cb + tig    ];
                ah[mt][1] = Ahi[(rw + gid + 8)*QP + cb + tig    ];
                ah[mt][2] = Ahi[(rw + gid    )*QP + cb + tig + 4];
                ah[mt][3] = Ahi[(rw + gid + 8)*QP + cb + tig + 4];
                al[mt][0] = Alo[(rw + gid    )*QP + cb + tig    ];
                al[mt][1] = Alo[(rw + gid + 8)*QP + cb + tig    ];
                al[mt][2] = Alo[(rw + gid    )*QP + cb + tig + 4];
                al[mt][3] = Alo[(rw + gid + 8)*QP + cb + tig + 4];
            }

            uint32_t bh[8][2], bl[8][2];
            #pragma unroll
            for (int nt = 0; nt < 8; nt++) {
                bh[nt][0] = Bhi[(nt*8 + gid)*QP + cb + tig    ];
                bh[nt][1] = Bhi[(nt*8 + gid)*QP + cb + tig + 4];
                bl[nt][0] = Blo[(nt*8 + gid)*QP + cb + tig    ];
                bl[nt][1] = Blo[(nt*8 + gid)*QP + cb + tig + 4];
            }

            #pragma unroll
            for (int mt = 0; mt < 2; mt++)
                #pragma unroll
                for (int nt = 0; nt < 8; nt++) {
                    mma_bf16(d[mt][nt], ah[mt], bh[nt]);   // hi*hi
                    mma_bf16(d[mt][nt], ah[mt], bl[nt]);   // hi*lo
                    mma_bf16(d[mt][nt], al[mt], bh[nt]);   // lo*hi
                }
        }
    }

    #pragma unroll
    for (int mt = 0; mt < 2; mt++) {
        const int r0 = m0 + wid*32 + mt*16 + gid;
        #pragma unroll
        for (int nt = 0; nt < 8; nt++) {
            const int c0 = nt*8 + 2*tig;
            *(float2*)&out[(size_t)r0      * H_ + c0] = make_float2(d[mt][nt][0], d[mt][nt][1]);
            *(float2*)&out[(size_t)(r0+8) * H_ + c0] = make_float2(d[mt][nt][2], d[mt][nt][3]);
        }
    }
}

// ---------------------------------------------------------------------------
// Flash attention on tensor cores — bf16 m16n8k16 hi/lo split (unchanged R11).
// ---------------------------------------------------------------------------
#define KPITCH 36
#define VPITCH 72
#define GWORDS (2*64*KPITCH + 2*32*VPITCH)   // 9216 words per group

#define BAR_SYNC(id) asm volatile("bar.sync %0, %1;" :: "r"(id), "r"(128) : "memory")

__global__ __launch_bounds__(256) void attn_mma_kernel(float* __restrict__ out)
{
    extern __shared__ uint32_t shb[];

    const int b    = blockIdx.y;
    const int p    = blockIdx.x;
    const int tid  = threadIdx.x;
    const int w    = tid >> 5;
    const int g    = w >> 2;            // warp group 0/1
    const int wg   = w & 3;             // warp within group
    const int lane = tid & 31;
    const int gid  = lane >> 2;
    const int tig  = lane & 3;
    const int w16  = wg * 16;
    const int ltid = tid & 127;

    const int krow = ltid >> 1;            // 0..63 (K row)
    const int kcb  = (ltid & 1) * 32;      // col block 0/32 (h)
    const int vkp  = ltid >> 2;            // 0..31 (V key-pair row)
    const int vcb  = (ltid & 3) * 16;      // h block 0/16/32/48

    uint32_t* Khi = shb + g*GWORDS;        // 64*36
    uint32_t* Klo = Khi + 64*KPITCH;       // 64*36
    uint32_t* Vhi = Klo + 64*KPITCH;       // 32*72
    uint32_t* Vlo = Vhi + 32*VPITCH;       // 32*72

    float* Osm = (float*)(shb + GWORDS);   // 64 x 66 (in group 1's dead K bufs)
    float* Mm  = Osm + 64*66;              // 64
    float* Lm  = Mm + 64;                  // 64

    for (int pick = 0; pick < 2; pick++) {
        const int qtile = pick ? (NQT - 1 - p) : p;

        const float* Qg = g_Q + (size_t)(b*T_ + qtile*64 + w16) * H_;
        uint32_t qh[4][4], ql[4][4];
        #pragma unroll
        for (int ks = 0; ks < 4; ks++) {
            float2 f0 = *(const float2*)&Qg[ gid     *H_ + ks*16 + 2*tig    ];
            float2 f1 = *(const float2*)&Qg[(gid + 8)*H_ + ks*16 + 2*tig    ];
            float2 f2 = *(const float2*)&Qg[ gid     *H_ + ks*16 + 2*tig + 8];
            float2 f3 = *(const float2*)&Qg[(gid + 8)*H_ + ks*16 + 2*tig + 8];
            qh[ks][0] = pack_hilo(f0.x, f0.y, ql[ks][0]);
            qh[ks][1] = pack_hilo(f1.x, f1.y, ql[ks][1]);
            qh[ks][2] = pack_hilo(f2.x, f2.y, ql[ks][2]);
            qh[ks][3] = pack_hilo(f3.x, f3.y, ql[ks][3]);
        }

        float o[8][4] = {};
        float mst[2] = {-1e30f, -1e30f};
        float lst[2] = {0.0f, 0.0f};

        for (int kt = g; kt <= qtile; kt += 2) {
            const float* Kg = g_K + (size_t)(b*T_ + kt*64) * H_;
            const float* Vg = g_V + (size_t)(b*T_ + kt*64) * H_;
            float4 kf[8];
            #pragma unroll
            for (int i = 0; i < 8; i++)
                kf[i] = *(const float4*)&Kg[krow*H_ + kcb + 4*i];
            float4 va[4], vb[4];
            #pragma unroll
            for (int i = 0; i < 4; i++) {
                va[i] = *(const float4*)&Vg[(2*vkp    )*H_ + vcb + 4*i];
                vb[i] = *(const float4*)&Vg[(2*vkp + 1)*H_ + vcb + 4*i];
            }
            BAR_SYNC(g+1);
            #pragma unroll
            for (int i = 0; i < 8; i++) {
                const int c = (kcb >> 1) + 2*i;
                uint32_t lo;
                Khi[krow*KPITCH + c    ] = pack_hilo(kf[i].x, kf[i].y, lo);
                Klo[krow*KPITCH + c    ] = lo;
                Khi[krow*KPITCH + c + 1] = pack_hilo(kf[i].z, kf[i].w, lo);
                Klo[krow*KPITCH + c + 1] = lo;
            }
            #pragma unroll
            for (int i = 0; i < 4; i++) {
                const float* pa = (const float*)&va[i];
                const float* pb = (const float*)&vb[i];
                #pragma unroll
                for (int e = 0; e < 4; e++) {
                    uint32_t lo;
                    Vhi[vkp*VPITCH + vcb + 4*i + e] = pack_hilo(pa[e], pb[e], lo);
                    Vlo[vkp*VPITCH + vcb + 4*i + e] = lo;
                }
            }
            BAR_SYNC(g+1);

            float s[8][4] = {};
            #pragma unroll
            for (int ks = 0; ks < 4; ks++) {
                #pragma unroll
                for (int nt = 0; nt < 8; nt++) {
                    const int kr = (nt*8 + gid)*KPITCH + ks*8 + tig;
                    uint32_t bh[2] = { Khi[kr], Khi[kr + 4] };
                    uint32_t bl[2] = { Klo[kr], Klo[kr + 4] };
                    mma_bf16(s[nt], qh[ks], bh);
                    mma_bf16(s[nt], qh[ks], bl);
                    mma_bf16(s[nt], ql[ks], bh);
                }
            }

            if (kt == qtile) {
                #pragma unroll
                for (int nt = 0; nt < 8; nt++) {
                    const int c0 = nt*8 + 2*tig;
                    if (c0     > w16 + gid    ) s[nt][0] = -1e30f;
                    if (c0 + 1 > w16 + gid    ) s[nt][1] = -1e30f;
                    if (c0     > w16 + gid + 8) s[nt][2] = -1e30f;
                    if (c0 + 1 > w16 + gid + 8) s[nt][3] = -1e30f;
                }
            }

            float mx0 = -1e30f, mx1 = -1e30f;
            #pragma unroll
            for (int nt = 0; nt < 8; nt++) {
                mx0 = fmaxf(mx0, fmaxf(s[nt][0], s[nt][1]));
                mx1 = fmaxf(mx1, fmaxf(s[nt][2], s[nt][3]));
            }
            mx0 = fmaxf(mx0, __shfl_xor_sync(0xffffffffu, mx0, 1));
            mx0 = fmaxf(mx0, __shfl_xor_sync(0xffffffffu, mx0, 2));
            mx1 = fmaxf(mx1, __shfl_xor_sync(0xffffffffu, mx1, 1));
            mx1 = fmaxf(mx1, __shfl_xor_sync(0xffffffffu, mx1, 2));
            const float mn0 = fmaxf(mst[0], mx0);
            const float mn1 = fmaxf(mst[1], mx1);
            const float sc0 = __expf(mst[0] - mn0);
            const float sc1 = __expf(mst[1] - mn1);

            float sum0 = 0.0f, sum1 = 0.0f;
            uint32_t ph[16], plr[16];
            #pragma unroll
            for (int nt = 0; nt < 8; nt++) {
                float p0 = __expf(s[nt][0] - mn0);
                float p1 = __expf(s[nt][1] - mn0);
                float p2 = __expf(s[nt][2] - mn1);
                float p3 = __expf(s[nt][3] - mn1);
                sum0 += p0 + p1;
                sum1 += p2 + p3;
                ph[2*nt    ] = pack_hilo(p0, p1, plr[2*nt    ]);
                ph[2*nt + 1] = pack_hilo(p2, p3, plr[2*nt + 1]);
            }
            sum0 += __shfl_xor_sync(0xffffffffu, sum0, 1);
            sum0 += __shfl_xor_sync(0xffffffffu, sum0, 2);
            sum1 += __shfl_xor_sync(0xffffffffu, sum1, 1);
            sum1 += __shfl_xor_sync(0xffffffffu, sum1, 2);
            lst[0] = lst[0]*sc0 + sum0;  mst[0] = mn0;
            lst[1] = lst[1]*sc1 + sum1;  mst[1] = mn1;
            #pragma unroll
            for (int nt = 0; nt < 8; nt++) {
                o[nt][0] *= sc0; o[nt][1] *= sc0;
                o[nt][2] *= sc1; o[nt][3] *= sc1;
            }

            #pragma unroll
            for (int ks = 0; ks < 4; ks++) {
                #pragma unroll
                for (int nt = 0; nt < 8; nt++) {
                    const int v0 = (ks*8 + tig)*VPITCH + nt*8 + gid;
                    const int v1 = v0 + 4*VPITCH;
                    uint32_t vh[2] = { Vhi[v0], Vhi[v1] };
                    uint32_t vl[2] = { Vlo[v0], Vlo[v1] };
                    mma_bf16(o[nt], &ph[4*ks],  vh);
                    mma_bf16(o[nt], &ph[4*ks],  vl);
                    mma_bf16(o[nt], &plr[4*ks], vh);
                }
            }
        }

        if (g == 1) {
            #pragma unroll
            for (int nt = 0; nt < 8; nt++) {
                const int c0 = nt*8 + 2*tig;
                *(float2*)&Osm[(w16 + gid    )*66 + c0] = make_float2(o[nt][0], o[nt][1]);
                *(float2*)&Osm[(w16 + gid + 8)*66 + c0] = make_float2(o[nt][2], o[nt][3]);
            }
            Mm[w16 + gid    ] = mst[0];  Lm[w16 + gid    ] = lst[0];
            Mm[w16 + gid + 8] = mst[1];  Lm[w16 + gid + 8] = lst[1];
        }
        __syncthreads();
        if (g == 0) {
            const float m1a = Mm[w16 + gid    ], l1a = Lm[w16 + gid    ];
            const float m1b = Mm[w16 + gid + 8], l1b = Lm[w16 + gid + 8];
            const float mF0 = fmaxf(mst[0], m1a);
            const float mF1 = fmaxf(mst[1], m1b);
            const float a00 = __expf(mst[0] - mF0), a01 = __expf(m1a - mF0);
            const float a10 = __expf(mst[1] - mF1), a11 = __expf(m1b - mF1);
            const float inv0 = 1.0f / (lst[0]*a00 + l1a*a01);
            const float inv1 = 1.0f / (lst[1]*a10 + l1b*a11);
            const size_t r0 = (size_t)(b*T_ + qtile*64 + w16 + gid);
            #pragma unroll
            for (int nt = 0; nt < 8; nt++) {
                const int c0 = nt*8 + 2*tig;
                float2 u0 = *(const float2*)&Osm[(w16 + gid    )*66 + c0];
                float2 u1 = *(const float2*)&Osm[(w16 + gid + 8)*66 + c0];
                *(float2*)&out[ r0      * H_ + c0] =
                    make_float2((o[nt][0]*a00 + u0.x*a01)*inv0,
                                (o[nt][1]*a00 + u0.y*a01)*inv0);
                *(float2*)&out[(r0 + 8) * H_ + c0] =
                    make_float2((o[nt][2]*a10 + u1.x*a11)*inv1,
                                (o[nt][3]*a10 + u1.y*a11)*inv1);
            }
        }
        __syncthreads();
    }
}

// ---------------------------------------------------------------------------
extern "C" void kernel_launch(void* const* d_in, const int* in_sizes, int n_in,
                              void* d_out, int out_size)
{
    const float* x  = (const float*)d_in[0];
    const float* Wk = (const float*)d_in[1];
    const float* Wq = (const float*)d_in[2];
    const float* Wv = (const float*)d_in[3];
    float* out = (float*)d_out;

    const int smem_qkv  = (2*128*QP + 2*64*QP) * (int)sizeof(uint32_t);  // 30720 B
    const int smem_attn = 2 * GWORDS * (int)sizeof(uint32_t);            // 73728 B
    cudaFuncSetAttribute(qkv_mma_kernel, cudaFuncAttributeMaxDynamicSharedMemorySize,
                         smem_qkv);
    cudaFuncSetAttribute(attn_mma_kernel, cudaFuncAttributeMaxDynamicSharedMemorySize,
                         smem_attn);

    qkv_mma_kernel<<<dim3(BT_/128, 3), 128, smem_qkv>>>(x, Wk, Wq, Wv);
    attn_mma_kernel<<<dim3(NQT/2, B_), 256, smem_attn>>>(out);
}